// round 13
// baseline (speedup 1.0000x reference)
#include <cuda_runtime.h>
#include <cuda_bf16.h>
#include <stdint.h>

// ---------------------------------------------------------------------------
// SEALNetwork fully fused: one CTA per graph runs all 3 GNN layers + pooling;
// h lives in shared memory throughout.
//   out = (Ain.h.inv)@Wn^T + (Aout.h.inv)@Wo^T + h@Wr^T + (ci.bn+co.bo).inv
// Adjacency = packed u8 counts (exact in bf16); bf16 hi/lo split elsewhere.
// R13: 8 warps x (64x32) warp tiles (LDSM wavefronts/MMA 1.33 -> 1.0; smem
// BW was the binding pipe), single live accumulator set (inv folded into
// Hin/Hout stores; root parked in L2-resident global scratch).
// ---------------------------------------------------------------------------

#define N_NODES 32768
#define N_EDGES 524288
#define NG      256
#define NPG     128
#define HD      128
#define NL      3
#define NC      16
#define BUFB    32768
#define ADJ_EL  (NG * NPG * NPG)
#define NT      256           // threads per CTA

__device__ int           g_cin[N_NODES];
__device__ int           g_cout[N_NODES];
__device__ float         g_l1[NG];
__device__ unsigned char g_adj[2][ADJ_EL];   // [0]=masked(in), [1]=out
__device__ float         g_root[NG * NPG * HD];   // 16MB scratch (L2-resident)
__device__ int           g_ei64;
__device__ int           g_mk_kind;          // 0=u8/bool 1=i32 2=f32

// ---------------------------------------------------------------------------
__device__ __forceinline__ uint32_t smem_u32(const void* p) {
    uint32_t a;
    asm("{ .reg .u64 t; cvta.to.shared.u64 t, %1; cvt.u32.u64 %0, t; }"
        : "=r"(a) : "l"(p));
    return a;
}

__device__ __forceinline__ void ldm_x4(uint32_t& r0, uint32_t& r1,
                                       uint32_t& r2, uint32_t& r3,
                                       uint32_t addr) {
    asm volatile("ldmatrix.sync.aligned.m8n8.x4.shared.b16 {%0,%1,%2,%3}, [%4];"
                 : "=r"(r0), "=r"(r1), "=r"(r2), "=r"(r3) : "r"(addr));
}

__device__ __forceinline__ void ldm_x4t(uint32_t& r0, uint32_t& r1,
                                        uint32_t& r2, uint32_t& r3,
                                        uint32_t addr) {
    asm volatile(
        "ldmatrix.sync.aligned.m8n8.x4.trans.shared.b16 {%0,%1,%2,%3}, [%4];"
        : "=r"(r0), "=r"(r1), "=r"(r2), "=r"(r3) : "r"(addr));
}

__device__ __forceinline__ void mma_bf16(float* c, const uint32_t* a,
                                         uint32_t b0, uint32_t b1) {
    asm volatile(
        "mma.sync.aligned.m16n8k16.row.col.f32.bf16.bf16.f32 "
        "{%0,%1,%2,%3}, {%4,%5,%6,%7}, {%8,%9}, {%0,%1,%2,%3};"
        : "+f"(c[0]), "+f"(c[1]), "+f"(c[2]), "+f"(c[3])
        : "r"(a[0]), "r"(a[1]), "r"(a[2]), "r"(a[3]), "r"(b0), "r"(b1));
}

__device__ __forceinline__ uint32_t bf2pack(float a, float b) {
    unsigned short lo = __bfloat16_as_ushort(__float2bfloat16(a));
    unsigned short hi = __bfloat16_as_ushort(__float2bfloat16(b));
    return (uint32_t)lo | ((uint32_t)hi << 16);
}

__device__ __forceinline__ uint32_t swz(int r, int c) {
    return (uint32_t)(r * 256 + ((((c >> 3) ^ (r & 7)) << 4) | ((c & 7) * 2)));
}

// Fused 3-term split GEMM (64x32 warp tile): acc += A0*B0^T+A0*B1^T+A1*B0^T
__device__ __forceinline__ void pass3_nn(float acc[4][4][4],
                                         uint32_t A0b, uint32_t A1b,
                                         uint32_t B0b, uint32_t B1b,
                                         int m_blk, int n_blk, int lane) {
    int ar = lane & 15, ak = lane >> 4;
    int br = (lane & 7) + ((lane & 16) >> 1), bk = (lane & 8) >> 3;
    #pragma unroll
    for (int ks = 0; ks < 8; ks++) {
        uint32_t a0[4][4], a1[4][4];
        #pragma unroll
        for (int mt = 0; mt < 4; mt++) {
            int row = m_blk + mt * 16 + ar;
            uint32_t off = (uint32_t)(row * 256 + (((ks * 2 + ak) ^ (row & 7)) << 4));
            ldm_x4(a0[mt][0], a0[mt][1], a0[mt][2], a0[mt][3], A0b + off);
            ldm_x4(a1[mt][0], a1[mt][1], a1[mt][2], a1[mt][3], A1b + off);
        }
        uint32_t b0[4][2], b1[4][2];
        #pragma unroll
        for (int np = 0; np < 2; np++) {
            int row = n_blk + np * 16 + br;
            uint32_t off = (uint32_t)(row * 256 + (((ks * 2 + bk) ^ (row & 7)) << 4));
            uint32_t r0, r1, r2, r3;
            ldm_x4(r0, r1, r2, r3, B0b + off);
            b0[np * 2][0] = r0;     b0[np * 2][1] = r1;
            b0[np * 2 + 1][0] = r2; b0[np * 2 + 1][1] = r3;
            ldm_x4(r0, r1, r2, r3, B1b + off);
            b1[np * 2][0] = r0;     b1[np * 2][1] = r1;
            b1[np * 2 + 1][0] = r2; b1[np * 2 + 1][1] = r3;
        }
        #pragma unroll
        for (int mt = 0; mt < 4; mt++)
            #pragma unroll
            for (int nt = 0; nt < 4; nt++) {
                mma_bf16(acc[mt][nt], a0[mt], b0[nt][0], b0[nt][1]);
                mma_bf16(acc[mt][nt], a0[mt], b1[nt][0], b1[nt][1]);
                mma_bf16(acc[mt][nt], a1[mt], b0[nt][0], b0[nt][1]);
            }
    }
}

// Fused 2-term adjacency GEMM: acc += C*(B0 + B1), B row-major (trans).
__device__ __forceinline__ void pass2_nt(float acc[4][4][4], uint32_t Cb,
                                         uint32_t B0b, uint32_t B1b,
                                         int m_blk, int n_blk, int lane) {
    int ar = lane & 15, ak = lane >> 4;
    int tr = lane & 15, tn = lane >> 4;
    #pragma unroll
    for (int ks = 0; ks < 8; ks++) {
        uint32_t c[4][4];
        #pragma unroll
        for (int mt = 0; mt < 4; mt++) {
            int row = m_blk + mt * 16 + ar;
            uint32_t off = (uint32_t)(row * 256 + (((ks * 2 + ak) ^ (row & 7)) << 4));
            ldm_x4(c[mt][0], c[mt][1], c[mt][2], c[mt][3], Cb + off);
        }
        uint32_t p[4][2], q[4][2];
        #pragma unroll
        for (int np = 0; np < 2; np++) {
            int row = ks * 16 + tr;
            int ng = ((n_blk + np * 16) >> 3) + tn;
            uint32_t off = (uint32_t)(row * 256 + ((ng ^ (row & 7)) << 4));
            uint32_t r0, r1, r2, r3;
            ldm_x4t(r0, r1, r2, r3, B0b + off);
            p[np * 2][0] = r0;     p[np * 2][1] = r1;
            p[np * 2 + 1][0] = r2; p[np * 2 + 1][1] = r3;
            ldm_x4t(r0, r1, r2, r3, B1b + off);
            q[np * 2][0] = r0;     q[np * 2][1] = r1;
            q[np * 2 + 1][0] = r2; q[np * 2 + 1][1] = r3;
        }
        #pragma unroll
        for (int mt = 0; mt < 4; mt++)
            #pragma unroll
            for (int nt = 0; nt < 4; nt++) {
                mma_bf16(acc[mt][nt], c[mt], p[nt][0], p[nt][1]);
                mma_bf16(acc[mt][nt], c[mt], q[nt][0], q[nt][1]);
            }
    }
}

// ---------------------------------------------------------------------------
__global__ void detect_kernel(const unsigned int* __restrict__ ei_w,
                              const unsigned int* __restrict__ mk_w) {
    int lane = threadIdx.x;
    int odd = 0;
    for (int i = lane; i < 64; i += 32)
        if (ei_w[2 * i + 1] != 0u) odd = 1;
    unsigned m1 = __ballot_sync(0xffffffffu, odd);
    int f1 = 0, mb = 0;
    for (int i = lane; i < 256; i += 32) {
        unsigned w = mk_w[i];
        if (w == 0x3F800000u) f1 = 1;
        else if ((w >> 8) != 0u) mb = 1;
    }
    unsigned mf = __ballot_sync(0xffffffffu, f1);
    unsigned mm = __ballot_sync(0xffffffffu, mb);
    if (lane == 0) {
        g_ei64 = (m1 == 0u) ? 1 : 0;
        g_mk_kind = mf ? 2 : (mm ? 0 : 1);
    }
}

__device__ __forceinline__ int load_idx(const void* ei, int pos) {
    if (g_ei64) return (int)((const long long*)ei)[pos];
    return ((const int*)ei)[pos];
}
__device__ __forceinline__ bool load_mask(const void* mk, int e) {
    int kind = g_mk_kind;
    if (kind == 0) return ((const unsigned char*)mk)[e] != 0;
    if (kind == 1) return ((const int*)mk)[e] != 0;
    return ((const float*)mk)[e] != 0.0f;
}

__global__ void zero_all_kernel() {
    int stride = gridDim.x * blockDim.x;
    int i0 = blockIdx.x * blockDim.x + threadIdx.x;
    uint4 z = make_uint4(0, 0, 0, 0);
    for (int i = i0; i < ADJ_EL / 16; i += stride) {
        ((uint4*)g_adj[0])[i] = z;
        ((uint4*)g_adj[1])[i] = z;
    }
    for (int i = i0; i < N_NODES; i += stride) {
        g_cin[i] = 0;
        g_cout[i] = 0;
    }
}

__global__ void adj_build_kernel(const void* __restrict__ ei,
                                 const void* __restrict__ mk) {
    int e = blockIdx.x * blockDim.x + threadIdx.x;
    if (e >= N_EDGES) return;
    int t = load_idx(ei, N_EDGES + e);
    int s = load_idx(ei, e);
    if ((unsigned)t >= (unsigned)N_NODES) return;
    if ((unsigned)s >= (unsigned)N_NODES) return;
    if ((t >> 7) != (s >> 7)) return;
    int sel = load_mask(mk, e) ? 0 : 1;
    int idx = ((t >> 7) * NPG + (t & 127)) * NPG + (s & 127);
    atomicAdd(&((unsigned int*)g_adj[sel])[idx >> 2], 1u << ((idx & 3) * 8));
    atomicAdd(sel ? &g_cout[t] : &g_cin[t], 1);
}

// ---------------------------------------------------------------------------
// Fused network kernel: one CTA per graph, 256 threads (8 warps, 64x32 tiles).
// Buffers (32KB each): [0]C0 [1]C1 [2]D [3]A0 [4]A1 [5]W0 [6]W1
// fp32 S overlays [0..2]; fp32 P overlays [3..5].
// ---------------------------------------------------------------------------
#define FUSED_SMEM (7 * BUFB)

__global__ void __launch_bounds__(NT)
fused_kernel(const float* __restrict__ x,
             const float* __restrict__ Wn_, const float* __restrict__ bn_,
             const float* __restrict__ Wo_, const float* __restrict__ bo_,
             const float* __restrict__ Wr_,
             const float* __restrict__ lng_, const float* __restrict__ lnb_,
             const float* __restrict__ sIn,
             const float* __restrict__ flng, const float* __restrict__ flnb,
             const float* __restrict__ linw, const float* __restrict__ bias,
             float* __restrict__ dout) {
    extern __shared__ __align__(16) char dyn[];
    __shared__ float sbn[HD], sbo[HD];
    __shared__ float s_inv[NPG], s_ci[NPG], s_co[NPG];
    __shared__ float colsum[NC], xcs[NC];

    int tid = threadIdx.x;
    int w = tid >> 5, lane = tid & 31;
    int m_blk = (w >> 2) * 64, n_blk = (w & 3) * 32;
    int grp = lane >> 2, tig = lane & 3;
    int g = blockIdx.x, row0 = g * 128;

    uint32_t base = smem_u32(dyn);
    uint32_t C0 = base, C1 = base + BUFB, Dd = base + 2 * BUFB;
    uint32_t A0 = base + 3 * BUFB, A1 = base + 4 * BUFB;
    uint32_t W0 = base + 5 * BUFB, W1 = base + 6 * BUFB;
    float* S = (float*)dyn;
    float* P = (float*)(dyn + 3 * BUFB);
    float* rootG = g_root + (size_t)g * NPG * HD;

    // per-row degree data (constant across layers)
    if (tid < NPG) {
        float ci = (float)g_cin[row0 + tid];
        float co = (float)g_cout[row0 + tid];
        s_ci[tid] = ci;
        s_co[tid] = co;
        s_inv[tid] = 1.0f / fmaxf(ci + co, 1.0f);
    }

    // --- layer-0 h: split x into A0/A1 ---
    #pragma unroll
    for (int i = 0; i < 8; i++) {
        int gid = tid + i * NT;
        int r = gid >> 4, gq = gid & 15;
        const float* src = x + (size_t)(row0 + r) * HD + gq * 8;
        float v[8];
        *(float4*)(v)     = *(const float4*)(src);
        *(float4*)(v + 4) = *(const float4*)(src + 4);
        uint32_t hi[4], lo[4];
        #pragma unroll
        for (int j = 0; j < 4; j++) {
            float a = v[2 * j], b = v[2 * j + 1];
            __nv_bfloat16 ha = __float2bfloat16(a), hb = __float2bfloat16(b);
            hi[j] = (uint32_t)__bfloat16_as_ushort(ha)
                  | ((uint32_t)__bfloat16_as_ushort(hb) << 16);
            lo[j] = bf2pack(a - __bfloat162float(ha), b - __bfloat162float(hb));
        }
        uint32_t off = (uint32_t)(r * 256 + ((gq ^ (r & 7)) << 4));
        *(uint4*)((char*)dyn + (A0 - base) + off) = make_uint4(hi[0], hi[1], hi[2], hi[3]);
        *(uint4*)((char*)dyn + (A1 - base) + off) = make_uint4(lo[0], lo[1], lo[2], lo[3]);
    }

    float acc[4][4][4];

    #pragma unroll 1
    for (int l = 0; l < NL; l++) {
        const float* Wn = Wn_ + l * HD * HD;
        const float* Wo = Wo_ + l * HD * HD;
        const float* Wr = Wr_ + l * HD * HD;

        __syncthreads();
        if (tid < HD) { sbn[tid] = bn_[l * HD + tid]; sbo[tid] = bo_[l * HD + tid]; }

        // adjacency u8 -> bf16 into C0/C1
        #pragma unroll
        for (int sel = 0; sel < 2; sel++) {
            const unsigned char* src = g_adj[sel] + (size_t)g * NPG * NPG;
            uint32_t dst = (sel == 0) ? C0 : C1;
            #pragma unroll
            for (int i = 0; i < 8; i++) {
                int gid = tid + i * NT;
                int r = gid >> 4, gq = gid & 15;
                uint2 raw = *(const uint2*)(src + r * NPG + gq * 8);
                uint32_t p[4];
                p[0] = bf2pack((float)(raw.x & 255), (float)((raw.x >> 8) & 255));
                p[1] = bf2pack((float)((raw.x >> 16) & 255), (float)(raw.x >> 24));
                p[2] = bf2pack((float)(raw.y & 255), (float)((raw.y >> 8) & 255));
                p[3] = bf2pack((float)((raw.y >> 16) & 255), (float)(raw.y >> 24));
                uint32_t off = (uint32_t)(r * 256 + ((gq ^ (r & 7)) << 4));
                *(uint4*)((char*)dyn + (dst - base) + off) = make_uint4(p[0], p[1], p[2], p[3]);
            }
        }

        // Wr split into W0/W1
        #pragma unroll
        for (int i = 0; i < 8; i++) {
            int gid = tid + i * NT;
            int r = gid >> 4, gq = gid & 15;
            const float* src = Wr + (size_t)r * HD + gq * 8;
            float v[8];
            *(float4*)(v)     = *(const float4*)(src);
            *(float4*)(v + 4) = *(const float4*)(src + 4);
            uint32_t hi[4], lo[4];
            #pragma unroll
            for (int j = 0; j < 4; j++) {
                float a = v[2 * j], b = v[2 * j + 1];
                __nv_bfloat16 ha = __float2bfloat16(a), hb = __float2bfloat16(b);
                hi[j] = (uint32_t)__bfloat16_as_ushort(ha)
                      | ((uint32_t)__bfloat16_as_ushort(hb) << 16);
                lo[j] = bf2pack(a - __bfloat162float(ha), b - __bfloat162float(hb));
            }
            uint32_t off = (uint32_t)(r * 256 + ((gq ^ (r & 7)) << 4));
            *(uint4*)((char*)dyn + (W0 - base) + off) = make_uint4(hi[0], hi[1], hi[2], hi[3]);
            *(uint4*)((char*)dyn + (W1 - base) + off) = make_uint4(lo[0], lo[1], lo[2], lo[3]);
        }
        __syncthreads();

        // --- root = h @ Wr^T -> global scratch ---
        #pragma unroll
        for (int mt = 0; mt < 4; mt++)
            #pragma unroll
            for (int nt = 0; nt < 4; nt++)
                #pragma unroll
                for (int q2 = 0; q2 < 4; q2++) acc[mt][nt][q2] = 0.f;
        pass3_nn(acc, A0, A1, W0, W1, m_blk, n_blk, lane);
        #pragma unroll
        for (int mt = 0; mt < 4; mt++)
            #pragma unroll
            for (int half = 0; half < 2; half++) {
                int row = m_blk + mt * 16 + grp + half * 8;
                #pragma unroll
                for (int nt = 0; nt < 4; nt++) {
                    int cg = n_blk + nt * 8 + tig * 2;
                    *(float2*)(rootG + row * HD + cg) =
                        make_float2(acc[mt][nt][half * 2], acc[mt][nt][half * 2 + 1]);
                }
            }

        // --- Hin' = inv . (Ain @ h): store split -> C0(hi), Dd(lo) ---
        #pragma unroll
        for (int mt = 0; mt < 4; mt++)
            #pragma unroll
            for (int nt = 0; nt < 4; nt++)
                #pragma unroll
                for (int q2 = 0; q2 < 4; q2++) acc[mt][nt][q2] = 0.f;
        pass2_nt(acc, C0, A0, A1, m_blk, n_blk, lane);
        __syncthreads();
        #pragma unroll
        for (int mt = 0; mt < 4; mt++) {
            #pragma unroll
            for (int nt = 0; nt < 4; nt++) {
                int cg = n_blk + nt * 8 + tig * 2;
                #pragma unroll
                for (int half = 0; half < 2; half++) {
                    int row = m_blk + mt * 16 + grp + half * 8;
                    float inv = s_inv[row];
                    float a = acc[mt][nt][half * 2] * inv;
                    float b = acc[mt][nt][half * 2 + 1] * inv;
                    __nv_bfloat16 ha = __float2bfloat16(a), hb = __float2bfloat16(b);
                    uint32_t off = swz(row, cg);
                    *(uint32_t*)((char*)dyn + (C0 - base) + off) =
                        (uint32_t)__bfloat16_as_ushort(ha)
                        | ((uint32_t)__bfloat16_as_ushort(hb) << 16);
                    *(uint32_t*)((char*)dyn + (Dd - base) + off) =
                        bf2pack(a - __bfloat162float(ha), b - __bfloat162float(hb));
                }
            }
        }

        // --- Hout' = inv . (Aout @ h): store split -> C1(hi), A1(lo) ---
        #pragma unroll
        for (int mt = 0; mt < 4; mt++)
            #pragma unroll
            for (int nt = 0; nt < 4; nt++)
                #pragma unroll
                for (int q2 = 0; q2 < 4; q2++) acc[mt][nt][q2] = 0.f;
        pass2_nt(acc, C1, A0, A1, m_blk, n_blk, lane);
        __syncthreads();
        #pragma unroll
        for (int mt = 0; mt < 4; mt++) {
            #pragma unroll
            for (int nt = 0; nt < 4; nt++) {
                int cg = n_blk + nt * 8 + tig * 2;
                #pragma unroll
                for (int half = 0; half < 2; half++) {
                    int row = m_blk + mt * 16 + grp + half * 8;
                    float inv = s_inv[row];
                    float a = acc[mt][nt][half * 2] * inv;
                    float b = acc[mt][nt][half * 2 + 1] * inv;
                    __nv_bfloat16 ha = __float2bfloat16(a), hb = __float2bfloat16(b);
                    uint32_t off = swz(row, cg);
                    *(uint32_t*)((char*)dyn + (C1 - base) + off) =
                        (uint32_t)__bfloat16_as_ushort(ha)
                        | ((uint32_t)__bfloat16_as_ushort(hb) << 16);
                    *(uint32_t*)((char*)dyn + (A1 - base) + off) =
                        bf2pack(a - __bfloat162float(ha), b - __bfloat162float(hb));
                }
            }
        }
        __syncthreads();

        // --- agg = Hin' @ Wn^T + Hout' @ Wo^T (one accumulator) ---
        #pragma unroll
        for (int mt = 0; mt < 4; mt++)
            #pragma unroll
            for (int nt = 0; nt < 4; nt++)
                #pragma unroll
                for (int q2 = 0; q2 < 4; q2++) acc[mt][nt][q2] = 0.f;

        const float* Wptr[2] = {Wn, Wo};
        #pragma unroll 1
        for (int m = 0; m < 2; m++) {
            const float* Wm = Wptr[m];
            #pragma unroll
            for (int i = 0; i < 8; i++) {
                int gid = tid + i * NT;
                int r = gid >> 4, gq = gid & 15;
                const float* src = Wm + (size_t)r * HD + gq * 8;
                float v[8];
                *(float4*)(v)     = *(const float4*)(src);
                *(float4*)(v + 4) = *(const float4*)(src + 4);
                uint32_t hi[4], lo[4];
                #pragma unroll
                for (int j = 0; j < 4; j++) {
                    float a = v[2 * j], b = v[2 * j + 1];
                    __nv_bfloat16 ha = __float2bfloat16(a), hb = __float2bfloat16(b);
                    hi[j] = (uint32_t)__bfloat16_as_ushort(ha)
                          | ((uint32_t)__bfloat16_as_ushort(hb) << 16);
                    lo[j] = bf2pack(a - __bfloat162float(ha),
                                    b - __bfloat162float(hb));
                }
                uint32_t off = (uint32_t)(r * 256 + ((gq ^ (r & 7)) << 4));
                *(uint4*)((char*)dyn + (W0 - base) + off) = make_uint4(hi[0], hi[1], hi[2], hi[3]);
                *(uint4*)((char*)dyn + (W1 - base) + off) = make_uint4(lo[0], lo[1], lo[2], lo[3]);
            }
            __syncthreads();

            uint32_t Hhi = (m == 0) ? C0 : C1;
            uint32_t Hlo = (m == 0) ? Dd : A1;
            pass3_nn(acc, Hhi, Hlo, W0, W1, m_blk, n_blk, lane);
            __syncthreads();
        }

        // epilogue: val = acc + root + (ci*bn + co*bo)*inv -> S
        #pragma unroll
        for (int mt = 0; mt < 4; mt++) {
            #pragma unroll
            for (int half = 0; half < 2; half++) {
                int row = m_blk + mt * 16 + grp + half * 8;
                float ci = s_ci[row], co = s_co[row], inv = s_inv[row];
                #pragma unroll
                for (int nt = 0; nt < 4; nt++) {
                    int cg = n_blk + nt * 8 + tig * 2;
                    float2 rt = *(const float2*)(rootG + row * HD + cg);
                    float v0 = acc[mt][nt][half * 2]     + rt.x
                             + (ci * sbn[cg]     + co * sbo[cg])     * inv;
                    float v1 = acc[mt][nt][half * 2 + 1] + rt.y
                             + (ci * sbn[cg + 1] + co * sbo[cg + 1]) * inv;
                    S[row * 132 + cg]     = v0;
                    S[row * 132 + cg + 1] = v1;
                }
            }
        }
        __syncthreads();

        // LayerNorm + ReLU (2 threads/row); write next-layer h or final P
        {
            int row = tid >> 1, q = tid & 1;
            const float* Sr = S + row * 132 + q * 64;
            float v[64];
            float sum = 0.f, sq = 0.f;
            #pragma unroll
            for (int j = 0; j < 64; j++) {
                v[j] = Sr[j];
                sum += v[j];
                sq  += v[j] * v[j];
            }
            sum += __shfl_xor_sync(0xffffffffu, sum, 1);
            sq  += __shfl_xor_sync(0xffffffffu, sq, 1);
            float mu   = sum * (1.0f / 128.0f);
            float var  = sq * (1.0f / 128.0f) - mu * mu;
            float rstd = rsqrtf(var + 1e-5f);

            const float* gma = lng_ + l * HD + q * 64;
            const float* bta = lnb_ + l * HD + q * 64;
            if (l < NL - 1) {
                #pragma unroll
                for (int j = 0; j < 64; j += 2) {
                    float o0 = fmaxf((v[j]     - mu) * rstd * gma[j]     + bta[j],     0.f);
                    float o1 = fmaxf((v[j + 1] - mu) * rstd * gma[j + 1] + bta[j + 1], 0.f);
                    int c = q * 64 + j;
                    uint32_t off = swz(row, c);
                    __nv_bfloat16 h0 = __float2bfloat16(o0), h1 = __float2bfloat16(o1);
                    *(uint32_t*)((char*)dyn + (A0 - base) + off) =
                        (uint32_t)__bfloat16_as_ushort(h0)
                        | ((uint32_t)__bfloat16_as_ushort(h1) << 16);
                    *(uint32_t*)((char*)dyn + (A1 - base) + off) =
                        bf2pack(o0 - __bfloat162float(h0), o1 - __bfloat162float(h1));
                }
            } else {
                float* Pr = P + row * 132 + q * 64;
                #pragma unroll
                for (int j = 0; j < 64; j += 4) {
                    float o0 = fmaxf((v[j]     - mu) * rstd * gma[j]     + bta[j],     0.f);
                    float o1 = fmaxf((v[j + 1] - mu) * rstd * gma[j + 1] + bta[j + 1], 0.f);
                    float o2 = fmaxf((v[j + 2] - mu) * rstd * gma[j + 2] + bta[j + 2], 0.f);
                    float o3 = fmaxf((v[j + 3] - mu) * rstd * gma[j + 3] + bta[j + 3], 0.f);
                    *(float4*)(Pr + j) = make_float4(o0, o1, o2, o3);
                }
            }
        }
    }

    // =================== pooling head (in-CTA) ===================
    __syncthreads();
    float* sdP = (float*)dyn;
    float* plP = (float*)(dyn + 8192);

    #pragma unroll
    for (int i = 0; i < 2; i++) {
        int t4 = tid + i * NT;
        *(float4*)(sdP + t4 * 4) =
            *(const float4*)(sIn + (size_t)g * NPG * NC + t4 * 4);
    }
    __syncthreads();

    if (tid < NC) {
        float cs = 0.f;
        for (int n = 0; n < NPG; n++) cs += sdP[n * NC + tid];
        colsum[tid] = cs;
    }

    {
        int hcol = tid & 127, cgrp = tid >> 7;   // cgrp 0..1, 8 channels each
        float pacc[8] = {0, 0, 0, 0, 0, 0, 0, 0};
        #pragma unroll 4
        for (int n = 0; n < NPG; n++) {
            float xv = P[n * 132 + hcol];
            #pragma unroll
            for (int c = 0; c < 8; c++)
                pacc[c] = fmaf(sdP[n * NC + cgrp * 8 + c], xv, pacc[c]);
        }
        #pragma unroll
        for (int c = 0; c < 8; c++)
            plP[(cgrp * 8 + c) * 128 + hcol] = pacc[c];
    }
    __syncthreads();

    for (int rr = w * 2; rr < w * 2 + 2; rr++) {   // 8 warps x 2 channels
        float4 v = *(float4*)(plP + rr * 128 + lane * 4);
        float sum = v.x + v.y + v.z + v.w;
        float sq  = v.x * v.x + v.y * v.y + v.z * v.z + v.w * v.w;
        #pragma unroll
        for (int o = 16; o; o >>= 1) {
            sum += __shfl_xor_sync(0xffffffffu, sum, o);
            sq  += __shfl_xor_sync(0xffffffffu, sq,  o);
        }
        float mu   = sum * (1.0f / 128.0f);
        float var  = sq * (1.0f / 128.0f) - mu * mu;
        float rstd = rsqrtf(var + 1e-5f);
        int f = lane * 4;
        float dot = ((v.x - mu) * rstd * flng[f + 0] + flnb[f + 0]) * linw[f + 0]
                  + ((v.y - mu) * rstd * flng[f + 1] + flnb[f + 1]) * linw[f + 1]
                  + ((v.z - mu) * rstd * flng[f + 2] + flnb[f + 2]) * linw[f + 2]
                  + ((v.w - mu) * rstd * flng[f + 3] + flnb[f + 3]) * linw[f + 3];
        #pragma unroll
        for (int o = 16; o; o >>= 1) dot += __shfl_xor_sync(0xffffffffu, dot, o);
        if (lane == 0) xcs[rr] = dot;
    }
    __syncthreads();

    if (tid == 0) {
        float ov = 0.f, l1 = 0.f, dn = 0.f;
        #pragma unroll
        for (int c = 0; c < NC; c++) {
            float mflag = (colsum[c] > 0.f) ? 1.f : 0.f;
            float v = xcs[c] * mflag;
            dout[257 + g * NC + c] = v;
            ov += v;
            l1 += fabsf(v);
            dn += mflag;
        }
        dout[g] = ov + bias[0];
        g_l1[g] = l1 / (dn + 1e-7f);
    }
}

// losses = 0.01*(sum|Wo|+sum|bo|) + 0.01*mean_g(l1[g])
__global__ void loss_kernel(const float* __restrict__ Wo,
                            const float* __restrict__ bo,
                            float* __restrict__ dout) {
    __shared__ float red[256];
    __shared__ float sreg;
    int tid = threadIdx.x;
    float rs = 0.f;
    for (int i = tid; i < NL * HD * HD; i += 256) rs += fabsf(Wo[i]);
    for (int i = tid; i < NL * HD; i += 256)      rs += fabsf(bo[i]);
    red[tid] = rs;
    __syncthreads();
    for (int o = 128; o; o >>= 1) {
        if (tid < o) red[tid] += red[tid + o];
        __syncthreads();
    }
    if (tid == 0) sreg = red[0];
    __syncthreads();
    float ls = (tid < NG) ? g_l1[tid] : 0.f;
    red[tid] = ls;
    __syncthreads();
    for (int o = 128; o; o >>= 1) {
        if (tid < o) red[tid] += red[tid + o];
        __syncthreads();
    }
    if (tid == 0)
        dout[256] = 0.01f * sreg + 0.01f * (red[0] / (float)NG);
}

// ---------------------------------------------------------------------------
extern "C" void kernel_launch(void* const* d_in, const int* in_sizes, int n_in,
                              void* d_out, int out_size) {
    const float* x    = (const float*)d_in[0];
    const void*  ei   = d_in[1];
    const void*  mk   = d_in[2];
    const float* s    = (const float*)d_in[3];
    const float* Wn   = (const float*)d_in[5];
    const float* bn   = (const float*)d_in[6];
    const float* Wo   = (const float*)d_in[7];
    const float* bo   = (const float*)d_in[8];
    const float* Wr   = (const float*)d_in[9];
    const float* lng  = (const float*)d_in[10];
    const float* lnb  = (const float*)d_in[11];
    const float* flng = (const float*)d_in[12];
    const float* flnb = (const float*)d_in[13];
    const float* linw = (const float*)d_in[14];
    const float* bias = (const float*)d_in[15];
    float* out = (float*)d_out;

    cudaFuncSetAttribute(fused_kernel,
                         cudaFuncAttributeMaxDynamicSharedMemorySize, FUSED_SMEM);

    detect_kernel<<<1, 32>>>((const unsigned int*)ei, (const unsigned int*)mk);
    zero_all_kernel<<<1024, 256>>>();
    adj_build_kernel<<<N_EDGES / 256, 256>>>(ei, mk);

    fused_kernel<<<NG, NT, FUSED_SMEM>>>(
        x, Wn, bn, Wo, bo, Wr, lng, lnb,
        s, flng, flnb, linw, bias, out);

    loss_kernel<<<1, 256>>>(Wo, bo, out);
}

// round 14
// speedup vs baseline: 1.0926x; 1.0926x over previous
#include <cuda_runtime.h>
#include <cuda_bf16.h>
#include <stdint.h>

// ---------------------------------------------------------------------------
// SEALNetwork fully fused: one CTA per graph runs all 3 GNN layers + pooling;
// h lives in shared memory throughout.
//   agg = (Ain.h).Wn^T + (Aout.h).Wo^T + cin (x) bn + cout (x) bo
// Adjacency = packed u8 counts (exact in bf16); bf16 hi/lo split elsewhere.
// R14: revert to R11 16-warp/32x32 config (R13's 8-warp regressed: occ 12%).
// NEW: prep kernels pre-split all 9 weight matrices and pre-convert per-graph
// adjacency to bf16, stored as PRE-SWIZZLED smem images -> fused kernel's
// staging loops are pure linear uint4 copies (no cvt math, 256x dedup).
// ---------------------------------------------------------------------------

#define N_NODES 32768
#define N_EDGES 524288
#define NG      256
#define NPG     128
#define HD      128
#define NL      3
#define NC      16
#define BUFB    32768
#define ADJ_EL  (NG * NPG * NPG)

__device__ int           g_cin[N_NODES];
__device__ int           g_cout[N_NODES];
__device__ float         g_l1[NG];
__device__ unsigned char g_adj[2][ADJ_EL];        // [0]=masked(in), [1]=out
__device__ __nv_bfloat16 g_aimg[2][NG][16384];    // pre-swizzled adj images
__device__ __nv_bfloat16 g_wimg[NL][3][2][16384]; // [l][Wn/Wo/Wr][hi/lo]
__device__ int           g_ei64;
__device__ int           g_mk_kind;               // 0=u8/bool 1=i32 2=f32

// ---------------------------------------------------------------------------
__device__ __forceinline__ uint32_t smem_u32(const void* p) {
    uint32_t a;
    asm("{ .reg .u64 t; cvta.to.shared.u64 t, %1; cvt.u32.u64 %0, t; }"
        : "=r"(a) : "l"(p));
    return a;
}

__device__ __forceinline__ void ldm_x4(uint32_t& r0, uint32_t& r1,
                                       uint32_t& r2, uint32_t& r3,
                                       uint32_t addr) {
    asm volatile("ldmatrix.sync.aligned.m8n8.x4.shared.b16 {%0,%1,%2,%3}, [%4];"
                 : "=r"(r0), "=r"(r1), "=r"(r2), "=r"(r3) : "r"(addr));
}

__device__ __forceinline__ void ldm_x4t(uint32_t& r0, uint32_t& r1,
                                        uint32_t& r2, uint32_t& r3,
                                        uint32_t addr) {
    asm volatile(
        "ldmatrix.sync.aligned.m8n8.x4.trans.shared.b16 {%0,%1,%2,%3}, [%4];"
        : "=r"(r0), "=r"(r1), "=r"(r2), "=r"(r3) : "r"(addr));
}

__device__ __forceinline__ void mma_bf16(float* c, const uint32_t* a,
                                         uint32_t b0, uint32_t b1) {
    asm volatile(
        "mma.sync.aligned.m16n8k16.row.col.f32.bf16.bf16.f32 "
        "{%0,%1,%2,%3}, {%4,%5,%6,%7}, {%8,%9}, {%0,%1,%2,%3};"
        : "+f"(c[0]), "+f"(c[1]), "+f"(c[2]), "+f"(c[3])
        : "r"(a[0]), "r"(a[1]), "r"(a[2]), "r"(a[3]), "r"(b0), "r"(b1));
}

__device__ __forceinline__ uint32_t bf2pack(float a, float b) {
    unsigned short lo = __bfloat16_as_ushort(__float2bfloat16(a));
    unsigned short hi = __bfloat16_as_ushort(__float2bfloat16(b));
    return (uint32_t)lo | ((uint32_t)hi << 16);
}

__device__ __forceinline__ uint32_t swz(int r, int c) {
    return (uint32_t)(r * 256 + ((((c >> 3) ^ (r & 7)) << 4) | ((c & 7) * 2)));
}

// Fused 3-term split GEMM: acc += A0*B0^T + A0*B1^T + A1*B0^T.
__device__ __forceinline__ void pass3_nn(float acc[2][4][4],
                                         uint32_t A0b, uint32_t A1b,
                                         uint32_t B0b, uint32_t B1b,
                                         int m_blk, int n_blk, int lane) {
    int ar = lane & 15, ak = lane >> 4;
    int br = (lane & 7) + ((lane & 16) >> 1), bk = (lane & 8) >> 3;
    #pragma unroll
    for (int ks = 0; ks < 8; ks++) {
        uint32_t a0[2][4], a1[2][4];
        #pragma unroll
        for (int mt = 0; mt < 2; mt++) {
            int row = m_blk + mt * 16 + ar;
            uint32_t off = (uint32_t)(row * 256 + (((ks * 2 + ak) ^ (row & 7)) << 4));
            ldm_x4(a0[mt][0], a0[mt][1], a0[mt][2], a0[mt][3], A0b + off);
            ldm_x4(a1[mt][0], a1[mt][1], a1[mt][2], a1[mt][3], A1b + off);
        }
        uint32_t b0[4][2], b1[4][2];
        #pragma unroll
        for (int np = 0; np < 2; np++) {
            int row = n_blk + np * 16 + br;
            uint32_t off = (uint32_t)(row * 256 + (((ks * 2 + bk) ^ (row & 7)) << 4));
            uint32_t r0, r1, r2, r3;
            ldm_x4(r0, r1, r2, r3, B0b + off);
            b0[np * 2][0] = r0;     b0[np * 2][1] = r1;
            b0[np * 2 + 1][0] = r2; b0[np * 2 + 1][1] = r3;
            ldm_x4(r0, r1, r2, r3, B1b + off);
            b1[np * 2][0] = r0;     b1[np * 2][1] = r1;
            b1[np * 2 + 1][0] = r2; b1[np * 2 + 1][1] = r3;
        }
        #pragma unroll
        for (int mt = 0; mt < 2; mt++)
            #pragma unroll
            for (int nt = 0; nt < 4; nt++) {
                mma_bf16(acc[mt][nt], a0[mt], b0[nt][0], b0[nt][1]);
                mma_bf16(acc[mt][nt], a0[mt], b1[nt][0], b1[nt][1]);
                mma_bf16(acc[mt][nt], a1[mt], b0[nt][0], b0[nt][1]);
            }
    }
}

// Fused 2-term adjacency GEMM: acc += C*(B0 + B1), B row-major (trans).
__device__ __forceinline__ void pass2_nt(float acc[2][4][4], uint32_t Cb,
                                         uint32_t B0b, uint32_t B1b,
                                         int m_blk, int n_blk, int lane) {
    int ar = lane & 15, ak = lane >> 4;
    int tr = lane & 15, tn = lane >> 4;
    #pragma unroll
    for (int ks = 0; ks < 8; ks++) {
        uint32_t c[2][4];
        #pragma unroll
        for (int mt = 0; mt < 2; mt++) {
            int row = m_blk + mt * 16 + ar;
            uint32_t off = (uint32_t)(row * 256 + (((ks * 2 + ak) ^ (row & 7)) << 4));
            ldm_x4(c[mt][0], c[mt][1], c[mt][2], c[mt][3], Cb + off);
        }
        uint32_t p[4][2], q[4][2];
        #pragma unroll
        for (int np = 0; np < 2; np++) {
            int row = ks * 16 + tr;
            int ng = ((n_blk + np * 16) >> 3) + tn;
            uint32_t off = (uint32_t)(row * 256 + ((ng ^ (row & 7)) << 4));
            uint32_t r0, r1, r2, r3;
            ldm_x4t(r0, r1, r2, r3, B0b + off);
            p[np * 2][0] = r0;     p[np * 2][1] = r1;
            p[np * 2 + 1][0] = r2; p[np * 2 + 1][1] = r3;
            ldm_x4t(r0, r1, r2, r3, B1b + off);
            q[np * 2][0] = r0;     q[np * 2][1] = r1;
            q[np * 2 + 1][0] = r2; q[np * 2 + 1][1] = r3;
        }
        #pragma unroll
        for (int mt = 0; mt < 2; mt++)
            #pragma unroll
            for (int nt = 0; nt < 4; nt++) {
                mma_bf16(acc[mt][nt], c[mt], p[nt][0], p[nt][1]);
                mma_bf16(acc[mt][nt], c[mt], q[nt][0], q[nt][1]);
            }
    }
}

// ---------------------------------------------------------------------------
__global__ void detect_kernel(const unsigned int* __restrict__ ei_w,
                              const unsigned int* __restrict__ mk_w) {
    int lane = threadIdx.x;
    int odd = 0;
    for (int i = lane; i < 64; i += 32)
        if (ei_w[2 * i + 1] != 0u) odd = 1;
    unsigned m1 = __ballot_sync(0xffffffffu, odd);
    int f1 = 0, mb = 0;
    for (int i = lane; i < 256; i += 32) {
        unsigned w = mk_w[i];
        if (w == 0x3F800000u) f1 = 1;
        else if ((w >> 8) != 0u) mb = 1;
    }
    unsigned mf = __ballot_sync(0xffffffffu, f1);
    unsigned mm = __ballot_sync(0xffffffffu, mb);
    if (lane == 0) {
        g_ei64 = (m1 == 0u) ? 1 : 0;
        g_mk_kind = mf ? 2 : (mm ? 0 : 1);
    }
}

__device__ __forceinline__ int load_idx(const void* ei, int pos) {
    if (g_ei64) return (int)((const long long*)ei)[pos];
    return ((const int*)ei)[pos];
}
__device__ __forceinline__ bool load_mask(const void* mk, int e) {
    int kind = g_mk_kind;
    if (kind == 0) return ((const unsigned char*)mk)[e] != 0;
    if (kind == 1) return ((const int*)mk)[e] != 0;
    return ((const float*)mk)[e] != 0.0f;
}

__global__ void zero_all_kernel() {
    int stride = gridDim.x * blockDim.x;
    int i0 = blockIdx.x * blockDim.x + threadIdx.x;
    uint4 z = make_uint4(0, 0, 0, 0);
    for (int i = i0; i < ADJ_EL / 16; i += stride) {
        ((uint4*)g_adj[0])[i] = z;
        ((uint4*)g_adj[1])[i] = z;
    }
    for (int i = i0; i < N_NODES; i += stride) {
        g_cin[i] = 0;
        g_cout[i] = 0;
    }
}

__global__ void adj_build_kernel(const void* __restrict__ ei,
                                 const void* __restrict__ mk) {
    int e = blockIdx.x * blockDim.x + threadIdx.x;
    if (e >= N_EDGES) return;
    int t = load_idx(ei, N_EDGES + e);
    int s = load_idx(ei, e);
    if ((unsigned)t >= (unsigned)N_NODES) return;
    if ((unsigned)s >= (unsigned)N_NODES) return;
    if ((t >> 7) != (s >> 7)) return;
    int sel = load_mask(mk, e) ? 0 : 1;
    int idx = ((t >> 7) * NPG + (t & 127)) * NPG + (s & 127);
    atomicAdd(&((unsigned int*)g_adj[sel])[idx >> 2], 1u << ((idx & 3) * 8));
    atomicAdd(sel ? &g_cout[t] : &g_cin[t], 1);
}

// pre-convert adjacency u8 -> bf16 smem-image (pre-swizzled). 1 block/graph.
__global__ void aprep_kernel() {
    int g = blockIdx.x, tid = threadIdx.x;
    #pragma unroll
    for (int sel = 0; sel < 2; sel++) {
        const unsigned char* src = g_adj[sel] + (size_t)g * NPG * NPG;
        char* dst = (char*)g_aimg[sel][g];
        #pragma unroll
        for (int i = 0; i < 8; i++) {
            int gid = tid + i * 256;
            int r = gid >> 4, gq = gid & 15;
            uint2 raw = *(const uint2*)(src + r * NPG + gq * 8);
            uint32_t p[4];
            p[0] = bf2pack((float)(raw.x & 255), (float)((raw.x >> 8) & 255));
            p[1] = bf2pack((float)((raw.x >> 16) & 255), (float)(raw.x >> 24));
            p[2] = bf2pack((float)(raw.y & 255), (float)((raw.y >> 8) & 255));
            p[3] = bf2pack((float)((raw.y >> 16) & 255), (float)(raw.y >> 24));
            uint32_t off = (uint32_t)(r * 256 + ((gq ^ (r & 7)) << 4));
            *(uint4*)(dst + off) = make_uint4(p[0], p[1], p[2], p[3]);
        }
    }
}

// pre-split all 9 weight matrices into hi/lo smem-images. 1 block/matrix.
__global__ void wprep_kernel(const float* __restrict__ Wn_,
                             const float* __restrict__ Wo_,
                             const float* __restrict__ Wr_) {
    int idx = blockIdx.x;              // 0..8
    int l = idx / 3, m = idx % 3;
    const float* src = ((m == 0) ? Wn_ : (m == 1) ? Wo_ : Wr_) + l * HD * HD;
    char* hiI = (char*)g_wimg[l][m][0];
    char* loI = (char*)g_wimg[l][m][1];
    int tid = threadIdx.x;
    #pragma unroll
    for (int i = 0; i < 4; i++) {
        int gid = tid + i * 512;
        int r = gid >> 4, gq = gid & 15;
        const float* s8 = src + (size_t)r * HD + gq * 8;
        float v[8];
        *(float4*)(v)     = *(const float4*)(s8);
        *(float4*)(v + 4) = *(const float4*)(s8 + 4);
        uint32_t hi[4], lo[4];
        #pragma unroll
        for (int j = 0; j < 4; j++) {
            float a = v[2 * j], b = v[2 * j + 1];
            __nv_bfloat16 ha = __float2bfloat16(a), hb = __float2bfloat16(b);
            hi[j] = (uint32_t)__bfloat16_as_ushort(ha)
                  | ((uint32_t)__bfloat16_as_ushort(hb) << 16);
            lo[j] = bf2pack(a - __bfloat162float(ha), b - __bfloat162float(hb));
        }
        uint32_t off = (uint32_t)(r * 256 + ((gq ^ (r & 7)) << 4));
        *(uint4*)(hiI + off) = make_uint4(hi[0], hi[1], hi[2], hi[3]);
        *(uint4*)(loI + off) = make_uint4(lo[0], lo[1], lo[2], lo[3]);
    }
}

// ---------------------------------------------------------------------------
#define FUSED_SMEM (7 * BUFB)

__global__ void __launch_bounds__(512)
fused_kernel(const float* __restrict__ x,
             const float* __restrict__ bn_, const float* __restrict__ bo_,
             const float* __restrict__ lng_, const float* __restrict__ lnb_,
             const float* __restrict__ sIn,
             const float* __restrict__ flng, const float* __restrict__ flnb,
             const float* __restrict__ linw, const float* __restrict__ bias,
             const float* __restrict__ WoL1, const float* __restrict__ boL1,
             float* __restrict__ dout) {
    extern __shared__ __align__(16) char dyn[];
    __shared__ float sbn[HD], sbo[HD];
    __shared__ float colsum[NC], xcs[NC];

    int tid = threadIdx.x;
    int w = tid >> 5, lane = tid & 31;
    int m_blk = (w >> 2) * 32, n_blk = (w & 3) * 32;
    int grp = lane >> 2, tig = lane & 3;
    int g = blockIdx.x, row0 = g * 128;

    uint32_t base = smem_u32(dyn);
    uint32_t C0 = base, C1 = base + BUFB, Dd = base + 2 * BUFB;
    uint32_t A0 = base + 3 * BUFB, A1 = base + 4 * BUFB;
    uint32_t W0 = base + 5 * BUFB, W1 = base + 6 * BUFB;
    float* S = (float*)dyn;
    float* P = (float*)(dyn + 3 * BUFB);

    uint4* c0d = (uint4*)((char*)dyn + (C0 - base));
    uint4* c1d = (uint4*)((char*)dyn + (C1 - base));
    uint4* w0d = (uint4*)((char*)dyn + (W0 - base));
    uint4* w1d = (uint4*)((char*)dyn + (W1 - base));

    // --- layer-0 h: split x into A0/A1 ---
    #pragma unroll
    for (int i = 0; i < 4; i++) {
        int gid = tid + i * 512;
        int r = gid >> 4, gq = gid & 15;
        const float* src = x + (size_t)(row0 + r) * HD + gq * 8;
        float v[8];
        *(float4*)(v)     = *(const float4*)(src);
        *(float4*)(v + 4) = *(const float4*)(src + 4);
        uint32_t hi[4], lo[4];
        #pragma unroll
        for (int j = 0; j < 4; j++) {
            float a = v[2 * j], b = v[2 * j + 1];
            __nv_bfloat16 ha = __float2bfloat16(a), hb = __float2bfloat16(b);
            hi[j] = (uint32_t)__bfloat16_as_ushort(ha)
                  | ((uint32_t)__bfloat16_as_ushort(hb) << 16);
            lo[j] = bf2pack(a - __bfloat162float(ha), b - __bfloat162float(hb));
        }
        uint32_t off = (uint32_t)(r * 256 + ((gq ^ (r & 7)) << 4));
        *(uint4*)((char*)dyn + (A0 - base) + off) = make_uint4(hi[0], hi[1], hi[2], hi[3]);
        *(uint4*)((char*)dyn + (A1 - base) + off) = make_uint4(lo[0], lo[1], lo[2], lo[3]);
    }

    #pragma unroll 1
    for (int l = 0; l < NL; l++) {
        __syncthreads();
        if (tid < HD) { sbn[tid] = bn_[l * HD + tid]; sbo[tid] = bo_[l * HD + tid]; }

        // adjacency images -> C0/C1 (linear copies)
        {
            const uint4* a0s = (const uint4*)g_aimg[0][g];
            const uint4* a1s = (const uint4*)g_aimg[1][g];
            #pragma unroll
            for (int i = 0; i < 4; i++) {
                int gid = tid + i * 512;
                c0d[gid] = a0s[gid];
                c1d[gid] = a1s[gid];
            }
        }
        // Wr images -> W0/W1 (linear copies)
        {
            const uint4* h0 = (const uint4*)g_wimg[l][2][0];
            const uint4* h1 = (const uint4*)g_wimg[l][2][1];
            #pragma unroll
            for (int i = 0; i < 4; i++) {
                int gid = tid + i * 512;
                w0d[gid] = h0[gid];
                w1d[gid] = h1[gid];
            }
        }
        __syncthreads();

        // root = h @ Wr^T (fused 3-term)
        float root[2][4][4];
        #pragma unroll
        for (int mt = 0; mt < 2; mt++)
            #pragma unroll
            for (int nt = 0; nt < 4; nt++)
                #pragma unroll
                for (int q = 0; q < 4; q++) root[mt][nt][q] = 0.f;
        pass3_nn(root, A0, A1, W0, W1, m_blk, n_blk, lane);

        // Hin = Ain @ (A0 + A1)
        float hacc[2][4][4];
        #pragma unroll
        for (int mt = 0; mt < 2; mt++)
            #pragma unroll
            for (int nt = 0; nt < 4; nt++)
                #pragma unroll
                for (int q = 0; q < 4; q++) hacc[mt][nt][q] = 0.f;
        pass2_nt(hacc, C0, A0, A1, m_blk, n_blk, lane);
        __syncthreads();
        #pragma unroll
        for (int mt = 0; mt < 2; mt++) {
            #pragma unroll
            for (int nt = 0; nt < 4; nt++) {
                int rg = m_blk + mt * 16 + grp;
                int cg = n_blk + nt * 8 + tig * 2;
                #pragma unroll
                for (int half = 0; half < 2; half++) {
                    int row = rg + half * 8;
                    float a = hacc[mt][nt][half * 2], b = hacc[mt][nt][half * 2 + 1];
                    __nv_bfloat16 ha = __float2bfloat16(a), hb = __float2bfloat16(b);
                    uint32_t off = swz(row, cg);
                    *(uint32_t*)((char*)dyn + (C0 - base) + off) =
                        (uint32_t)__bfloat16_as_ushort(ha)
                        | ((uint32_t)__bfloat16_as_ushort(hb) << 16);
                    *(uint32_t*)((char*)dyn + (Dd - base) + off) =
                        bf2pack(a - __bfloat162float(ha), b - __bfloat162float(hb));
                }
            }
        }

        // Hout = Aout @ (A0 + A1)
        #pragma unroll
        for (int mt = 0; mt < 2; mt++)
            #pragma unroll
            for (int nt = 0; nt < 4; nt++)
                #pragma unroll
                for (int q = 0; q < 4; q++) hacc[mt][nt][q] = 0.f;
        pass2_nt(hacc, C1, A0, A1, m_blk, n_blk, lane);
        __syncthreads();
        #pragma unroll
        for (int mt = 0; mt < 2; mt++) {
            #pragma unroll
            for (int nt = 0; nt < 4; nt++) {
                int rg = m_blk + mt * 16 + grp;
                int cg = n_blk + nt * 8 + tig * 2;
                #pragma unroll
                for (int half = 0; half < 2; half++) {
                    int row = rg + half * 8;
                    float a = hacc[mt][nt][half * 2], b = hacc[mt][nt][half * 2 + 1];
                    __nv_bfloat16 ha = __float2bfloat16(a), hb = __float2bfloat16(b);
                    uint32_t off = swz(row, cg);
                    *(uint32_t*)((char*)dyn + (C1 - base) + off) =
                        (uint32_t)__bfloat16_as_ushort(ha)
                        | ((uint32_t)__bfloat16_as_ushort(hb) << 16);
                    *(uint32_t*)((char*)dyn + (A1 - base) + off) =
                        bf2pack(a - __bfloat162float(ha), b - __bfloat162float(hb));
                }
            }
        }
        __syncthreads();

        // agg = Hin @ Wn^T + Hout @ Wo^T
        float agg[2][4][4];
        #pragma unroll
        for (int mt = 0; mt < 2; mt++)
            #pragma unroll
            for (int nt = 0; nt < 4; nt++)
                #pragma unroll
                for (int q = 0; q < 4; q++) agg[mt][nt][q] = 0.f;

        #pragma unroll 1
        for (int m = 0; m < 2; m++) {
            const uint4* h0 = (const uint4*)g_wimg[l][m][0];
            const uint4* h1 = (const uint4*)g_wimg[l][m][1];
            #pragma unroll
            for (int i = 0; i < 4; i++) {
                int gid = tid + i * 512;
                w0d[gid] = h0[gid];
                w1d[gid] = h1[gid];
            }
            __syncthreads();

            uint32_t Hhi = (m == 0) ? C0 : C1;
            uint32_t Hlo = (m == 0) ? Dd : A1;
            pass3_nn(agg, Hhi, Hlo, W0, W1, m_blk, n_blk, lane);
            __syncthreads();
        }

        // epilogue -> S (fp32, overlays C0/C1/D)
        #pragma unroll
        for (int mt = 0; mt < 2; mt++) {
            int rg = m_blk + mt * 16 + grp;
            #pragma unroll
            for (int half = 0; half < 2; half++) {
                int row = rg + half * 8;
                float ci = (float)g_cin[row0 + row];
                float co = (float)g_cout[row0 + row];
                float inv = 1.0f / fmaxf(ci + co, 1.0f);
                #pragma unroll
                for (int nt = 0; nt < 4; nt++) {
                    int cg = n_blk + nt * 8 + tig * 2;
                    float v0 = (agg[mt][nt][half * 2]     + ci * sbn[cg]
                                + co * sbo[cg]) * inv + root[mt][nt][half * 2];
                    float v1 = (agg[mt][nt][half * 2 + 1] + ci * sbn[cg + 1]
                                + co * sbo[cg + 1]) * inv + root[mt][nt][half * 2 + 1];
                    S[row * 132 + cg]     = v0;
                    S[row * 132 + cg + 1] = v1;
                }
            }
        }
        __syncthreads();

        // LayerNorm + ReLU (4 threads/row); write next-layer h or final P
        {
            int row = tid >> 2, q = tid & 3;
            const float* Sr = S + row * 132 + q * 32;
            float v[32];
            float sum = 0.f, sq = 0.f;
            #pragma unroll
            for (int j = 0; j < 32; j++) {
                v[j] = Sr[j];
                sum += v[j];
                sq  += v[j] * v[j];
            }
            sum += __shfl_xor_sync(0xffffffffu, sum, 1);
            sum += __shfl_xor_sync(0xffffffffu, sum, 2);
            sq  += __shfl_xor_sync(0xffffffffu, sq, 1);
            sq  += __shfl_xor_sync(0xffffffffu, sq, 2);
            float mu   = sum * (1.0f / 128.0f);
            float var  = sq * (1.0f / 128.0f) - mu * mu;
            float rstd = rsqrtf(var + 1e-5f);

            const float* gma = lng_ + l * HD + q * 32;
            const float* bta = lnb_ + l * HD + q * 32;
            if (l < NL - 1) {
                #pragma unroll
                for (int j = 0; j < 32; j += 2) {
                    float o0 = fmaxf((v[j]     - mu) * rstd * gma[j]     + bta[j],     0.f);
                    float o1 = fmaxf((v[j + 1] - mu) * rstd * gma[j + 1] + bta[j + 1], 0.f);
                    int c = q * 32 + j;
                    uint32_t off = swz(row, c);
                    __nv_bfloat16 h0 = __float2bfloat16(o0), h1 = __float2bfloat16(o1);
                    *(uint32_t*)((char*)dyn + (A0 - base) + off) =
                        (uint32_t)__bfloat16_as_ushort(h0)
                        | ((uint32_t)__bfloat16_as_ushort(h1) << 16);
                    *(uint32_t*)((char*)dyn + (A1 - base) + off) =
                        bf2pack(o0 - __bfloat162float(h0), o1 - __bfloat162float(h1));
                }
            } else {
                float* Pr = P + row * 132 + q * 32;
                #pragma unroll
                for (int j = 0; j < 32; j += 4) {
                    float o0 = fmaxf((v[j]     - mu) * rstd * gma[j]     + bta[j],     0.f);
                    float o1 = fmaxf((v[j + 1] - mu) * rstd * gma[j + 1] + bta[j + 1], 0.f);
                    float o2 = fmaxf((v[j + 2] - mu) * rstd * gma[j + 2] + bta[j + 2], 0.f);
                    float o3 = fmaxf((v[j + 3] - mu) * rstd * gma[j + 3] + bta[j + 3], 0.f);
                    *(float4*)(Pr + j) = make_float4(o0, o1, o2, o3);
                }
            }
        }
    }

    // =================== pooling head (in-CTA) ===================
    __syncthreads();
    float* sdP = (float*)dyn;
    float* plP = (float*)(dyn + 8192);

    *(float4*)(sdP + tid * 4) =
        *(const float4*)(sIn + (size_t)g * NPG * NC + tid * 4);
    __syncthreads();

    if (tid < NC) {
        float cs = 0.f;
        for (int n = 0; n < NPG; n++) cs += sdP[n * NC + tid];
        colsum[tid] = cs;
    }

    {
        int hcol = tid & 127, cgrp = tid >> 7;
        float pacc[4] = {0.f, 0.f, 0.f, 0.f};
        #pragma unroll 4
        for (int n = 0; n < NPG; n++) {
            float xv = P[n * 132 + hcol];
            #pragma unroll
            for (int c = 0; c < 4; c++)
                pacc[c] = fmaf(sdP[n * NC + cgrp * 4 + c], xv, pacc[c]);
        }
        #pragma unroll
        for (int c = 0; c < 4; c++)
            plP[(cgrp * 4 + c) * 128 + hcol] = pacc[c];
    }
    __syncthreads();

    {
        int rr = w;
        float4 v = *(float4*)(plP + rr * 128 + lane * 4);
        float sum = v.x + v.y + v.z + v.w;
        float sq  = v.x * v.x + v.y * v.y + v.z * v.z + v.w * v.w;
        #pragma unroll
        for (int o = 16; o; o >>= 1) {
            sum += __shfl_xor_sync(0xffffffffu, sum, o);
            sq  += __shfl_xor_sync(0xffffffffu, sq,  o);
        }
        float mu   = sum * (1.0f / 128.0f);
        float var  = sq * (1.0f / 128.0f) - mu * mu;
        float rstd = rsqrtf(var + 1e-5f);
        int f = lane * 4;
        float dot = ((v.x - mu) * rstd * flng[f + 0] + flnb[f + 0]) * linw[f + 0]
                  + ((v.y - mu) * rstd * flng[f + 1] + flnb[f + 1]) * linw[f + 1]
                  + ((v.z - mu) * rstd * flng[f + 2] + flnb[f + 2]) * linw[f + 2]
                  + ((v.w - mu) * rstd * flng[f + 3] + flnb[f + 3]) * linw[f + 3];
        #pragma unroll
        for (int o = 16; o; o >>= 1) dot += __shfl_xor_sync(0xffffffffu, dot, o);
        if (lane == 0) xcs[rr] = dot;
    }
    __syncthreads();

    if (tid == 0) {
        float ov = 0.f, l1 = 0.f, dn = 0.f;
        #pragma unroll
        for (int c = 0; c < NC; c++) {
            float mflag = (colsum[c] > 0.f) ? 1.f : 0.f;
            float v = xcs[c] * mflag;
            dout[257 + g * NC + c] = v;
            ov += v;
            l1 += fabsf(v);
            dn += mflag;
        }
        dout[g] = ov + bias[0];
        g_l1[g] = l1 / (dn + 1e-7f);
    }
    (void)WoL1; (void)boL1;
}

// losses = 0.01*(sum|Wo|+sum|bo|) + 0.01*mean_g(l1[g])
__global__ void loss_kernel(const float* __restrict__ Wo,
                            const float* __restrict__ bo,
                            float* __restrict__ dout) {
    __shared__ float red[256];
    __shared__ float sreg;
    int tid = threadIdx.x;
    float rs = 0.f;
    for (int i = tid; i < NL * HD * HD; i += 256) rs += fabsf(Wo[i]);
    for (int i = tid; i < NL * HD; i += 256)      rs += fabsf(bo[i]);
    red[tid] = rs;
    __syncthreads();
    for (int o = 128; o; o >>= 1) {
        if (tid < o) red[tid] += red[tid + o];
        __syncthreads();
    }
    if (tid == 0) sreg = red[0];
    __syncthreads();
    float ls = (tid < NG) ? g_l1[tid] : 0.f;
    red[tid] = ls;
    __syncthreads();
    for (int o = 128; o; o >>= 1) {
        if (tid < o) red[tid] += red[tid + o];
        __syncthreads();
    }
    if (tid == 0)
        dout[256] = 0.01f * sreg + 0.01f * (red[0] / (float)NG);
}

// ---------------------------------------------------------------------------
extern "C" void kernel_launch(void* const* d_in, const int* in_sizes, int n_in,
                              void* d_out, int out_size) {
    const float* x    = (const float*)d_in[0];
    const void*  ei   = d_in[1];
    const void*  mk   = d_in[2];
    const float* s    = (const float*)d_in[3];
    const float* Wn   = (const float*)d_in[5];
    const float* bn   = (const float*)d_in[6];
    const float* Wo   = (const float*)d_in[7];
    const float* bo   = (const float*)d_in[8];
    const float* Wr   = (const float*)d_in[9];
    const float* lng  = (const float*)d_in[10];
    const float* lnb  = (const float*)d_in[11];
    const float* flng = (const float*)d_in[12];
    const float* flnb = (const float*)d_in[13];
    const float* linw = (const float*)d_in[14];
    const float* bias = (const float*)d_in[15];
    float* out = (float*)d_out;

    cudaFuncSetAttribute(fused_kernel,
                         cudaFuncAttributeMaxDynamicSharedMemorySize, FUSED_SMEM);

    detect_kernel<<<1, 32>>>((const unsigned int*)ei, (const unsigned int*)mk);
    zero_all_kernel<<<1024, 256>>>();
    wprep_kernel<<<9, 512>>>(Wn, Wo, Wr);
    adj_build_kernel<<<N_EDGES / 256, 256>>>(ei, mk);
    aprep_kernel<<<NG, 256>>>();

    fused_kernel<<<NG, 512, FUSED_SMEM>>>(
        x, bn, bo, lng, lnb,
        s, flng, flnb, linw, bias, Wo, bo, out);

    loss_kernel<<<1, 256>>>(Wo, bo, out);
}

// round 15
// speedup vs baseline: 1.1787x; 1.0788x over previous
#include <cuda_runtime.h>
#include <cuda_bf16.h>
#include <stdint.h>

// ---------------------------------------------------------------------------
// SEALNetwork fully fused: one CTA per graph runs all 3 GNN layers + pooling;
// h lives in shared memory throughout.
//   agg = (Ain.h).Wn^T + (Aout.h).Wo^T + cin (x) bn + cout (x) bo
// Adjacency = packed u8 counts (exact in bf16); bf16 hi/lo split elsewhere.
// R15: staging via cp.async.bulk DMA + mbarriers. Prefetches: layer-0 images
// overlap the x-split; Wn overlaps the adjacency passes (W free after root);
// Wo-hi prefetched into A0 (h-hi dead after Hout pass) overlapping agg-Wn.
// ---------------------------------------------------------------------------

#define N_NODES 32768
#define N_EDGES 524288
#define NG      256
#define NPG     128
#define HD      128
#define NL      3
#define NC      16
#define BUFB    32768
#define ADJ_EL  (NG * NPG * NPG)

__device__ int           g_cin[N_NODES];
__device__ int           g_cout[N_NODES];
__device__ float         g_l1[NG];
__device__ unsigned char g_adj[2][ADJ_EL];        // [0]=masked(in), [1]=out
__device__ __align__(16) __nv_bfloat16 g_aimg[2][NG][16384];    // adj images
__device__ __align__(16) __nv_bfloat16 g_wimg[NL][3][2][16384]; // [l][m][hi/lo]
__device__ int           g_ei64;
__device__ int           g_mk_kind;               // 0=u8/bool 1=i32 2=f32

// ---------------------------------------------------------------------------
__device__ __forceinline__ uint32_t smem_u32(const void* p) {
    uint32_t a;
    asm("{ .reg .u64 t; cvta.to.shared.u64 t, %1; cvt.u32.u64 %0, t; }"
        : "=r"(a) : "l"(p));
    return a;
}

__device__ __forceinline__ void ldm_x4(uint32_t& r0, uint32_t& r1,
                                       uint32_t& r2, uint32_t& r3,
                                       uint32_t addr) {
    asm volatile("ldmatrix.sync.aligned.m8n8.x4.shared.b16 {%0,%1,%2,%3}, [%4];"
                 : "=r"(r0), "=r"(r1), "=r"(r2), "=r"(r3) : "r"(addr));
}

__device__ __forceinline__ void ldm_x4t(uint32_t& r0, uint32_t& r1,
                                        uint32_t& r2, uint32_t& r3,
                                        uint32_t addr) {
    asm volatile(
        "ldmatrix.sync.aligned.m8n8.x4.trans.shared.b16 {%0,%1,%2,%3}, [%4];"
        : "=r"(r0), "=r"(r1), "=r"(r2), "=r"(r3) : "r"(addr));
}

__device__ __forceinline__ void mma_bf16(float* c, const uint32_t* a,
                                         uint32_t b0, uint32_t b1) {
    asm volatile(
        "mma.sync.aligned.m16n8k16.row.col.f32.bf16.bf16.f32 "
        "{%0,%1,%2,%3}, {%4,%5,%6,%7}, {%8,%9}, {%0,%1,%2,%3};"
        : "+f"(c[0]), "+f"(c[1]), "+f"(c[2]), "+f"(c[3])
        : "r"(a[0]), "r"(a[1]), "r"(a[2]), "r"(a[3]), "r"(b0), "r"(b1));
}

__device__ __forceinline__ uint32_t bf2pack(float a, float b) {
    unsigned short lo = __bfloat16_as_ushort(__float2bfloat16(a));
    unsigned short hi = __bfloat16_as_ushort(__float2bfloat16(b));
    return (uint32_t)lo | ((uint32_t)hi << 16);
}

__device__ __forceinline__ uint32_t swz(int r, int c) {
    return (uint32_t)(r * 256 + ((((c >> 3) ^ (r & 7)) << 4) | ((c & 7) * 2)));
}

// ---- mbarrier + bulk-DMA helpers (sm_90 baseline PTX) ----
__device__ __forceinline__ void mbar_init(uint32_t a) {
    asm volatile("mbarrier.init.shared.b64 [%0], 1;" :: "r"(a) : "memory");
}
__device__ __forceinline__ void mbar_expect(uint32_t a, uint32_t bytes) {
    asm volatile("mbarrier.arrive.expect_tx.shared.b64 _, [%0], %1;"
                 :: "r"(a), "r"(bytes) : "memory");
}
__device__ __forceinline__ void mbar_wait(uint32_t a, uint32_t parity) {
    asm volatile(
        "{\n\t.reg .pred P;\n"
        "W%=:\n\t"
        "mbarrier.try_wait.parity.shared::cta.b64 P, [%0], %1;\n\t"
        "@!P bra W%=;\n\t}"
        :: "r"(a), "r"(parity) : "memory");
}
__device__ __forceinline__ void bulk_g2s(uint32_t dst, const void* src,
                                         uint32_t bytes, uint32_t mbar) {
    asm volatile(
        "cp.async.bulk.shared::cta.global.mbarrier::complete_tx::bytes "
        "[%0], [%1], %2, [%3];"
        :: "r"(dst), "l"(src), "r"(bytes), "r"(mbar) : "memory");
}

// Fused 3-term split GEMM: acc += A0*B0^T + A0*B1^T + A1*B0^T.
__device__ __forceinline__ void pass3_nn(float acc[2][4][4],
                                         uint32_t A0b, uint32_t A1b,
                                         uint32_t B0b, uint32_t B1b,
                                         int m_blk, int n_blk, int lane) {
    int ar = lane & 15, ak = lane >> 4;
    int br = (lane & 7) + ((lane & 16) >> 1), bk = (lane & 8) >> 3;
    #pragma unroll
    for (int ks = 0; ks < 8; ks++) {
        uint32_t a0[2][4], a1[2][4];
        #pragma unroll
        for (int mt = 0; mt < 2; mt++) {
            int row = m_blk + mt * 16 + ar;
            uint32_t off = (uint32_t)(row * 256 + (((ks * 2 + ak) ^ (row & 7)) << 4));
            ldm_x4(a0[mt][0], a0[mt][1], a0[mt][2], a0[mt][3], A0b + off);
            ldm_x4(a1[mt][0], a1[mt][1], a1[mt][2], a1[mt][3], A1b + off);
        }
        uint32_t b0[4][2], b1[4][2];
        #pragma unroll
        for (int np = 0; np < 2; np++) {
            int row = n_blk + np * 16 + br;
            uint32_t off = (uint32_t)(row * 256 + (((ks * 2 + bk) ^ (row & 7)) << 4));
            uint32_t r0, r1, r2, r3;
            ldm_x4(r0, r1, r2, r3, B0b + off);
            b0[np * 2][0] = r0;     b0[np * 2][1] = r1;
            b0[np * 2 + 1][0] = r2; b0[np * 2 + 1][1] = r3;
            ldm_x4(r0, r1, r2, r3, B1b + off);
            b1[np * 2][0] = r0;     b1[np * 2][1] = r1;
            b1[np * 2 + 1][0] = r2; b1[np * 2 + 1][1] = r3;
        }
        #pragma unroll
        for (int mt = 0; mt < 2; mt++)
            #pragma unroll
            for (int nt = 0; nt < 4; nt++) {
                mma_bf16(acc[mt][nt], a0[mt], b0[nt][0], b0[nt][1]);
                mma_bf16(acc[mt][nt], a0[mt], b1[nt][0], b1[nt][1]);
                mma_bf16(acc[mt][nt], a1[mt], b0[nt][0], b0[nt][1]);
            }
    }
}

// Fused 2-term adjacency GEMM: acc += C*(B0 + B1), B row-major (trans).
__device__ __forceinline__ void pass2_nt(float acc[2][4][4], uint32_t Cb,
                                         uint32_t B0b, uint32_t B1b,
                                         int m_blk, int n_blk, int lane) {
    int ar = lane & 15, ak = lane >> 4;
    int tr = lane & 15, tn = lane >> 4;
    #pragma unroll
    for (int ks = 0; ks < 8; ks++) {
        uint32_t c[2][4];
        #pragma unroll
        for (int mt = 0; mt < 2; mt++) {
            int row = m_blk + mt * 16 + ar;
            uint32_t off = (uint32_t)(row * 256 + (((ks * 2 + ak) ^ (row & 7)) << 4));
            ldm_x4(c[mt][0], c[mt][1], c[mt][2], c[mt][3], Cb + off);
        }
        uint32_t p[4][2], q[4][2];
        #pragma unroll
        for (int np = 0; np < 2; np++) {
            int row = ks * 16 + tr;
            int ng = ((n_blk + np * 16) >> 3) + tn;
            uint32_t off = (uint32_t)(row * 256 + ((ng ^ (row & 7)) << 4));
            uint32_t r0, r1, r2, r3;
            ldm_x4t(r0, r1, r2, r3, B0b + off);
            p[np * 2][0] = r0;     p[np * 2][1] = r1;
            p[np * 2 + 1][0] = r2; p[np * 2 + 1][1] = r3;
            ldm_x4t(r0, r1, r2, r3, B1b + off);
            q[np * 2][0] = r0;     q[np * 2][1] = r1;
            q[np * 2 + 1][0] = r2; q[np * 2 + 1][1] = r3;
        }
        #pragma unroll
        for (int mt = 0; mt < 2; mt++)
            #pragma unroll
            for (int nt = 0; nt < 4; nt++) {
                mma_bf16(acc[mt][nt], c[mt], p[nt][0], p[nt][1]);
                mma_bf16(acc[mt][nt], c[mt], q[nt][0], q[nt][1]);
            }
    }
}

// ---------------------------------------------------------------------------
__global__ void detect_kernel(const unsigned int* __restrict__ ei_w,
                              const unsigned int* __restrict__ mk_w) {
    int lane = threadIdx.x;
    int odd = 0;
    for (int i = lane; i < 64; i += 32)
        if (ei_w[2 * i + 1] != 0u) odd = 1;
    unsigned m1 = __ballot_sync(0xffffffffu, odd);
    int f1 = 0, mb = 0;
    for (int i = lane; i < 256; i += 32) {
        unsigned w = mk_w[i];
        if (w == 0x3F800000u) f1 = 1;
        else if ((w >> 8) != 0u) mb = 1;
    }
    unsigned mf = __ballot_sync(0xffffffffu, f1);
    unsigned mm = __ballot_sync(0xffffffffu, mb);
    if (lane == 0) {
        g_ei64 = (m1 == 0u) ? 1 : 0;
        g_mk_kind = mf ? 2 : (mm ? 0 : 1);
    }
}

__device__ __forceinline__ int load_idx(const void* ei, int pos) {
    if (g_ei64) return (int)((const long long*)ei)[pos];
    return ((const int*)ei)[pos];
}
__device__ __forceinline__ bool load_mask(const void* mk, int e) {
    int kind = g_mk_kind;
    if (kind == 0) return ((const unsigned char*)mk)[e] != 0;
    if (kind == 1) return ((const int*)mk)[e] != 0;
    return ((const float*)mk)[e] != 0.0f;
}

__global__ void zero_all_kernel() {
    int stride = gridDim.x * blockDim.x;
    int i0 = blockIdx.x * blockDim.x + threadIdx.x;
    uint4 z = make_uint4(0, 0, 0, 0);
    for (int i = i0; i < ADJ_EL / 16; i += stride) {
        ((uint4*)g_adj[0])[i] = z;
        ((uint4*)g_adj[1])[i] = z;
    }
    for (int i = i0; i < N_NODES; i += stride) {
        g_cin[i] = 0;
        g_cout[i] = 0;
    }
}

__global__ void adj_build_kernel(const void* __restrict__ ei,
                                 const void* __restrict__ mk) {
    int e = blockIdx.x * blockDim.x + threadIdx.x;
    if (e >= N_EDGES) return;
    int t = load_idx(ei, N_EDGES + e);
    int s = load_idx(ei, e);
    if ((unsigned)t >= (unsigned)N_NODES) return;
    if ((unsigned)s >= (unsigned)N_NODES) return;
    if ((t >> 7) != (s >> 7)) return;
    int sel = load_mask(mk, e) ? 0 : 1;
    int idx = ((t >> 7) * NPG + (t & 127)) * NPG + (s & 127);
    atomicAdd(&((unsigned int*)g_adj[sel])[idx >> 2], 1u << ((idx & 3) * 8));
    atomicAdd(sel ? &g_cout[t] : &g_cin[t], 1);
}

// pre-convert adjacency u8 -> bf16 smem-image (pre-swizzled). 1 block/graph.
__global__ void aprep_kernel() {
    int g = blockIdx.x, tid = threadIdx.x;
    #pragma unroll
    for (int sel = 0; sel < 2; sel++) {
        const unsigned char* src = g_adj[sel] + (size_t)g * NPG * NPG;
        char* dst = (char*)g_aimg[sel][g];
        #pragma unroll
        for (int i = 0; i < 8; i++) {
            int gid = tid + i * 256;
            int r = gid >> 4, gq = gid & 15;
            uint2 raw = *(const uint2*)(src + r * NPG + gq * 8);
            uint32_t p[4];
            p[0] = bf2pack((float)(raw.x & 255), (float)((raw.x >> 8) & 255));
            p[1] = bf2pack((float)((raw.x >> 16) & 255), (float)(raw.x >> 24));
            p[2] = bf2pack((float)(raw.y & 255), (float)((raw.y >> 8) & 255));
            p[3] = bf2pack((float)((raw.y >> 16) & 255), (float)(raw.y >> 24));
            uint32_t off = (uint32_t)(r * 256 + ((gq ^ (r & 7)) << 4));
            *(uint4*)(dst + off) = make_uint4(p[0], p[1], p[2], p[3]);
        }
    }
}

// pre-split all 9 weight matrices into hi/lo smem-images. 1 block/matrix.
__global__ void wprep_kernel(const float* __restrict__ Wn_,
                             const float* __restrict__ Wo_,
                             const float* __restrict__ Wr_) {
    int idx = blockIdx.x;              // 0..8
    int l = idx / 3, m = idx % 3;
    const float* src = ((m == 0) ? Wn_ : (m == 1) ? Wo_ : Wr_) + l * HD * HD;
    char* hiI = (char*)g_wimg[l][m][0];
    char* loI = (char*)g_wimg[l][m][1];
    int tid = threadIdx.x;
    #pragma unroll
    for (int i = 0; i < 4; i++) {
        int gid = tid + i * 512;
        int r = gid >> 4, gq = gid & 15;
        const float* s8 = src + (size_t)r * HD + gq * 8;
        float v[8];
        *(float4*)(v)     = *(const float4*)(s8);
        *(float4*)(v + 4) = *(const float4*)(s8 + 4);
        uint32_t hi[4], lo[4];
        #pragma unroll
        for (int j = 0; j < 4; j++) {
            float a = v[2 * j], b = v[2 * j + 1];
            __nv_bfloat16 ha = __float2bfloat16(a), hb = __float2bfloat16(b);
            hi[j] = (uint32_t)__bfloat16_as_ushort(ha)
                  | ((uint32_t)__bfloat16_as_ushort(hb) << 16);
            lo[j] = bf2pack(a - __bfloat162float(ha), b - __bfloat162float(hb));
        }
        uint32_t off = (uint32_t)(r * 256 + ((gq ^ (r & 7)) << 4));
        *(uint4*)(hiI + off) = make_uint4(hi[0], hi[1], hi[2], hi[3]);
        *(uint4*)(loI + off) = make_uint4(lo[0], lo[1], lo[2], lo[3]);
    }
}

// ---------------------------------------------------------------------------
#define FUSED_SMEM (7 * BUFB)

__global__ void __launch_bounds__(512)
fused_kernel(const float* __restrict__ x,
             const float* __restrict__ bn_, const float* __restrict__ bo_,
             const float* __restrict__ lng_, const float* __restrict__ lnb_,
             const float* __restrict__ sIn,
             const float* __restrict__ flng, const float* __restrict__ flnb,
             const float* __restrict__ linw, const float* __restrict__ bias,
             float* __restrict__ dout) {
    extern __shared__ __align__(16) char dyn[];
    __shared__ float sbn[HD], sbo[HD];
    __shared__ float colsum[NC], xcs[NC];
    __shared__ __align__(8) unsigned long long mbars[3];

    int tid = threadIdx.x;
    int w = tid >> 5, lane = tid & 31;
    int m_blk = (w >> 2) * 32, n_blk = (w & 3) * 32;
    int grp = lane >> 2, tig = lane & 3;
    int g = blockIdx.x, row0 = g * 128;

    uint32_t base = smem_u32(dyn);
    uint32_t C0 = base, C1 = base + BUFB, Dd = base + 2 * BUFB;
    uint32_t A0 = base + 3 * BUFB, A1 = base + 4 * BUFB;
    uint32_t W0 = base + 5 * BUFB, W1 = base + 6 * BUFB;
    float* S = (float*)dyn;
    float* P = (float*)(dyn + 3 * BUFB);

    uint32_t mbA = smem_u32(&mbars[0]);
    uint32_t mbB = smem_u32(&mbars[1]);
    uint32_t mbC = smem_u32(&mbars[2]);

    if (tid == 0) { mbar_init(mbA); mbar_init(mbB); mbar_init(mbC); }
    __syncthreads();

    int pa = 0, pb = 0, pc = 0;

    // issue layer-0 staging (adj + Wr) — overlaps the x-split below
    if (tid == 0) {
        mbar_expect(mbA, 4 * BUFB);
        bulk_g2s(C0, g_aimg[0][g], BUFB, mbA);
        bulk_g2s(C1, g_aimg[1][g], BUFB, mbA);
        bulk_g2s(W0, g_wimg[0][2][0], BUFB, mbA);
        bulk_g2s(W1, g_wimg[0][2][1], BUFB, mbA);
    }

    // --- layer-0 h: split x into A0/A1 ---
    #pragma unroll
    for (int i = 0; i < 4; i++) {
        int gid = tid + i * 512;
        int r = gid >> 4, gq = gid & 15;
        const float* src = x + (size_t)(row0 + r) * HD + gq * 8;
        float v[8];
        *(float4*)(v)     = *(const float4*)(src);
        *(float4*)(v + 4) = *(const float4*)(src + 4);
        uint32_t hi[4], lo[4];
        #pragma unroll
        for (int j = 0; j < 4; j++) {
            float a = v[2 * j], b = v[2 * j + 1];
            __nv_bfloat16 ha = __float2bfloat16(a), hb = __float2bfloat16(b);
            hi[j] = (uint32_t)__bfloat16_as_ushort(ha)
                  | ((uint32_t)__bfloat16_as_ushort(hb) << 16);
            lo[j] = bf2pack(a - __bfloat162float(ha), b - __bfloat162float(hb));
        }
        uint32_t off = (uint32_t)(r * 256 + ((gq ^ (r & 7)) << 4));
        *(uint4*)((char*)dyn + (A0 - base) + off) = make_uint4(hi[0], hi[1], hi[2], hi[3]);
        *(uint4*)((char*)dyn + (A1 - base) + off) = make_uint4(lo[0], lo[1], lo[2], lo[3]);
    }

    #pragma unroll 1
    for (int l = 0; l < NL; l++) {
        mbar_wait(mbA, (uint32_t)(pa & 1)); pa++;   // adj + Wr(l) ready
        if (tid < HD) { sbn[tid] = bn_[l * HD + tid]; sbo[tid] = bo_[l * HD + tid]; }
        __syncthreads();   // x-split / LN writes visible; bias loaded

        // root = h @ Wr^T (fused 3-term)
        float root[2][4][4];
        #pragma unroll
        for (int mt = 0; mt < 2; mt++)
            #pragma unroll
            for (int nt = 0; nt < 4; nt++)
                #pragma unroll
                for (int q = 0; q < 4; q++) root[mt][nt][q] = 0.f;
        pass3_nn(root, A0, A1, W0, W1, m_blk, n_blk, lane);
        __syncthreads();   // all warps done reading W0/W1
        if (tid == 0) {    // prefetch Wn -> W0/W1 (overlaps both adj passes)
            mbar_expect(mbB, 2 * BUFB);
            bulk_g2s(W0, g_wimg[l][0][0], BUFB, mbB);
            bulk_g2s(W1, g_wimg[l][0][1], BUFB, mbB);
        }

        // Hin = Ain @ (A0 + A1)
        float hacc[2][4][4];
        #pragma unroll
        for (int mt = 0; mt < 2; mt++)
            #pragma unroll
            for (int nt = 0; nt < 4; nt++)
                #pragma unroll
                for (int q = 0; q < 4; q++) hacc[mt][nt][q] = 0.f;
        pass2_nt(hacc, C0, A0, A1, m_blk, n_blk, lane);
        __syncthreads();   // all done reading C0 before overwrite
        #pragma unroll
        for (int mt = 0; mt < 2; mt++) {
            #pragma unroll
            for (int nt = 0; nt < 4; nt++) {
                int rg = m_blk + mt * 16 + grp;
                int cg = n_blk + nt * 8 + tig * 2;
                #pragma unroll
                for (int half = 0; half < 2; half++) {
                    int row = rg + half * 8;
                    float a = hacc[mt][nt][half * 2], b = hacc[mt][nt][half * 2 + 1];
                    __nv_bfloat16 ha = __float2bfloat16(a), hb = __float2bfloat16(b);
                    uint32_t off = swz(row, cg);
                    *(uint32_t*)((char*)dyn + (C0 - base) + off) =
                        (uint32_t)__bfloat16_as_ushort(ha)
                        | ((uint32_t)__bfloat16_as_ushort(hb) << 16);
                    *(uint32_t*)((char*)dyn + (Dd - base) + off) =
                        bf2pack(a - __bfloat162float(ha), b - __bfloat162float(hb));
                }
            }
        }

        // Hout = Aout @ (A0 + A1)
        #pragma unroll
        for (int mt = 0; mt < 2; mt++)
            #pragma unroll
            for (int nt = 0; nt < 4; nt++)
                #pragma unroll
                for (int q = 0; q < 4; q++) hacc[mt][nt][q] = 0.f;
        pass2_nt(hacc, C1, A0, A1, m_blk, n_blk, lane);
        __syncthreads();   // all done reading C1 + A0/A1 (h)
        if (tid == 0) {    // prefetch Wo-hi -> A0 (h-hi now dead)
            mbar_expect(mbC, BUFB);
            bulk_g2s(A0, g_wimg[l][1][0], BUFB, mbC);
        }
        #pragma unroll
        for (int mt = 0; mt < 2; mt++) {
            #pragma unroll
            for (int nt = 0; nt < 4; nt++) {
                int rg = m_blk + mt * 16 + grp;
                int cg = n_blk + nt * 8 + tig * 2;
                #pragma unroll
                for (int half = 0; half < 2; half++) {
                    int row = rg + half * 8;
                    float a = hacc[mt][nt][half * 2], b = hacc[mt][nt][half * 2 + 1];
                    __nv_bfloat16 ha = __float2bfloat16(a), hb = __float2bfloat16(b);
                    uint32_t off = swz(row, cg);
                    *(uint32_t*)((char*)dyn + (C1 - base) + off) =
                        (uint32_t)__bfloat16_as_ushort(ha)
                        | ((uint32_t)__bfloat16_as_ushort(hb) << 16);
                    *(uint32_t*)((char*)dyn + (A1 - base) + off) =
                        bf2pack(a - __bfloat162float(ha), b - __bfloat162float(hb));
                }
            }
        }
        __syncthreads();   // Hin/Hout stores visible
        mbar_wait(mbB, (uint32_t)(pb & 1)); pb++;   // Wn ready

        // agg = Hin @ Wn^T
        float agg[2][4][4];
        #pragma unroll
        for (int mt = 0; mt < 2; mt++)
            #pragma unroll
            for (int nt = 0; nt < 4; nt++)
                #pragma unroll
                for (int q = 0; q < 4; q++) agg[mt][nt][q] = 0.f;
        pass3_nn(agg, C0, Dd, W0, W1, m_blk, n_blk, lane);
        __syncthreads();   // done reading W1 (Wn-lo)
        if (tid == 0) {    // Wo-lo -> W1
            mbar_expect(mbA, BUFB);
            bulk_g2s(W1, g_wimg[l][1][1], BUFB, mbA);
        }
        mbar_wait(mbC, (uint32_t)(pc & 1)); pc++;   // Wo-hi in A0
        mbar_wait(mbA, (uint32_t)(pa & 1)); pa++;   // Wo-lo in W1

        // agg += Hout @ Wo^T  (Hhi=C1, Hlo=A1, Whi=A0, Wlo=W1)
        pass3_nn(agg, C1, A1, A0, W1, m_blk, n_blk, lane);
        __syncthreads();   // before epilogue overwrites S region (C0/C1/D)

        // epilogue -> S (fp32, overlays C0/C1/D)
        #pragma unroll
        for (int mt = 0; mt < 2; mt++) {
            int rg = m_blk + mt * 16 + grp;
            #pragma unroll
            for (int half = 0; half < 2; half++) {
                int row = rg + half * 8;
                float ci = (float)g_cin[row0 + row];
                float co = (float)g_cout[row0 + row];
                float inv = 1.0f / fmaxf(ci + co, 1.0f);
                #pragma unroll
                for (int nt = 0; nt < 4; nt++) {
                    int cg = n_blk + nt * 8 + tig * 2;
                    float v0 = (agg[mt][nt][half * 2]     + ci * sbn[cg]
                                + co * sbo[cg]) * inv + root[mt][nt][half * 2];
                    float v1 = (agg[mt][nt][half * 2 + 1] + ci * sbn[cg + 1]
                                + co * sbo[cg + 1]) * inv + root[mt][nt][half * 2 + 1];
                    S[row * 132 + cg]     = v0;
                    S[row * 132 + cg + 1] = v1;
                }
            }
        }
        __syncthreads();

        // LayerNorm + ReLU (4 threads/row); write next-layer h or final P
        {
            int row = tid >> 2, q = tid & 3;
            const float* Sr = S + row * 132 + q * 32;
            float v[32];
            float sum = 0.f, sq = 0.f;
            #pragma unroll
            for (int j = 0; j < 32; j++) {
                v[j] = Sr[j];
                sum += v[j];
                sq  += v[j] * v[j];
            }
            sum += __shfl_xor_sync(0xffffffffu, sum, 1);
            sum += __shfl_xor_sync(0xffffffffu, sum, 2);
            sq  += __shfl_xor_sync(0xffffffffu, sq, 1);
            sq  += __shfl_xor_sync(0xffffffffu, sq, 2);
            float mu   = sum * (1.0f / 128.0f);
            float var  = sq * (1.0f / 128.0f) - mu * mu;
            float rstd = rsqrtf(var + 1e-5f);

            const float* gma = lng_ + l * HD + q * 32;
            const float* bta = lnb_ + l * HD + q * 32;
            if (l < NL - 1) {
                #pragma unroll
                for (int j = 0; j < 32; j += 2) {
                    float o0 = fmaxf((v[j]     - mu) * rstd * gma[j]     + bta[j],     0.f);
                    float o1 = fmaxf((v[j + 1] - mu) * rstd * gma[j + 1] + bta[j + 1], 0.f);
                    int c = q * 32 + j;
                    uint32_t off = swz(row, c);
                    __nv_bfloat16 h0 = __float2bfloat16(o0), h1 = __float2bfloat16(o1);
                    *(uint32_t*)((char*)dyn + (A0 - base) + off) =
                        (uint32_t)__bfloat16_as_ushort(h0)
                        | ((uint32_t)__bfloat16_as_ushort(h1) << 16);
                    *(uint32_t*)((char*)dyn + (A1 - base) + off) =
                        bf2pack(o0 - __bfloat162float(h0), o1 - __bfloat162float(h1));
                }
            } else {
                float* Pr = P + row * 132 + q * 32;
                #pragma unroll
                for (int j = 0; j < 32; j += 4) {
                    float o0 = fmaxf((v[j]     - mu) * rstd * gma[j]     + bta[j],     0.f);
                    float o1 = fmaxf((v[j + 1] - mu) * rstd * gma[j + 1] + bta[j + 1], 0.f);
                    float o2 = fmaxf((v[j + 2] - mu) * rstd * gma[j + 2] + bta[j + 2], 0.f);
                    float o3 = fmaxf((v[j + 3] - mu) * rstd * gma[j + 3] + bta[j + 3], 0.f);
                    *(float4*)(Pr + j) = make_float4(o0, o1, o2, o3);
                }
            }
        }
        if (l < NL - 1) {
            __syncthreads();   // S reads done; C0/C1/W0/W1 free
            if (tid == 0) {    // next-layer adj + Wr
                mbar_expect(mbA, 4 * BUFB);
                bulk_g2s(C0, g_aimg[0][g], BUFB, mbA);
                bulk_g2s(C1, g_aimg[1][g], BUFB, mbA);
                bulk_g2s(W0, g_wimg[l + 1][2][0], BUFB, mbA);
                bulk_g2s(W1, g_wimg[l + 1][2][1], BUFB, mbA);
            }
        }
    }

    // =================== pooling head (in-CTA) ===================
    __syncthreads();
    float* sdP = (float*)dyn;
    float* plP = (float*)(dyn + 8192);

    *(float4*)(sdP + tid * 4) =
        *(const float4*)(sIn + (size_t)g * NPG * NC + tid * 4);
    __syncthreads();

    if (tid < NC) {
        float cs = 0.f;
        for (int n = 0; n < NPG; n++) cs += sdP[n * NC + tid];
        colsum[tid] = cs;
    }

    {
        int hcol = tid & 127, cgrp = tid >> 7;
        float pacc[4] = {0.f, 0.f, 0.f, 0.f};
        #pragma unroll 4
        for (int n = 0; n < NPG; n++) {
            float xv = P[n * 132 + hcol];
            #pragma unroll
            for (int c = 0; c < 4; c++)
                pacc[c] = fmaf(sdP[n * NC + cgrp * 4 + c], xv, pacc[c]);
        }
        #pragma unroll
        for (int c = 0; c < 4; c++)
            plP[(cgrp * 4 + c) * 128 + hcol] = pacc[c];
    }
    __syncthreads();

    {
        int rr = w;
        float4 v = *(float4*)(plP + rr * 128 + lane * 4);
        float sum = v.x + v.y + v.z + v.w;
        float sq  = v.x * v.x + v.y * v.y + v.z * v.z + v.w * v.w;
        #pragma unroll
        for (int o = 16; o; o >>= 1) {
            sum += __shfl_xor_sync(0xffffffffu, sum, o);
            sq  += __shfl_xor_sync(0xffffffffu, sq,  o);
        }
        float mu   = sum * (1.0f / 128.0f);
        float var  = sq * (1.0f / 128.0f) - mu * mu;
        float rstd = rsqrtf(var + 1e-5f);
        int f = lane * 4;
        float dot = ((v.x - mu) * rstd * flng[f + 0] + flnb[f + 0]) * linw[f + 0]
                  + ((v.y - mu) * rstd * flng[f + 1] + flnb[f + 1]) * linw[f + 1]
                  + ((v.z - mu) * rstd * flng[f + 2] + flnb[f + 2]) * linw[f + 2]
                  + ((v.w - mu) * rstd * flng[f + 3] + flnb[f + 3]) * linw[f + 3];
        #pragma unroll
        for (int o = 16; o; o >>= 1) dot += __shfl_xor_sync(0xffffffffu, dot, o);
        if (lane == 0) xcs[rr] = dot;
    }
    __syncthreads();

    if (tid == 0) {
        float ov = 0.f, l1 = 0.f, dn = 0.f;
        #pragma unroll
        for (int c = 0; c < NC; c++) {
            float mflag = (colsum[c] > 0.f) ? 1.f : 0.f;
            float v = xcs[c] * mflag;
            dout[257 + g * NC + c] = v;
            ov += v;
            l1 += fabsf(v);
            dn += mflag;
        }
        dout[g] = ov + bias[0];
        g_l1[g] = l1 / (dn + 1e-7f);
    }
}

// losses = 0.01*(sum|Wo|+sum|bo|) + 0.01*mean_g(l1[g])
__global__ void loss_kernel(const float* __restrict__ Wo,
                            const float* __restrict__ bo,
                            float* __restrict__ dout) {
    __shared__ float red[256];
    __shared__ float sreg;
    int tid = threadIdx.x;
    float rs = 0.f;
    for (int i = tid; i < NL * HD * HD; i += 256) rs += fabsf(Wo[i]);
    for (int i = tid; i < NL * HD; i += 256)      rs += fabsf(bo[i]);
    red[tid] = rs;
    __syncthreads();
    for (int o = 128; o; o >>= 1) {
        if (tid < o) red[tid] += red[tid + o];
        __syncthreads();
    }
    if (tid == 0) sreg = red[0];
    __syncthreads();
    float ls = (tid < NG) ? g_l1[tid] : 0.f;
    red[tid] = ls;
    __syncthreads();
    for (int o = 128; o; o >>= 1) {
        if (tid < o) red[tid] += red[tid + o];
        __syncthreads();
    }
    if (tid == 0)
        dout[256] = 0.01f * sreg + 0.01f * (red[0] / (float)NG);
}

// ---------------------------------------------------------------------------
extern "C" void kernel_launch(void* const* d_in, const int* in_sizes, int n_in,
                              void* d_out, int out_size) {
    const float* x    = (const float*)d_in[0];
    const void*  ei   = d_in[1];
    const void*  mk   = d_in[2];
    const float* s    = (const float*)d_in[3];
    const float* Wn   = (const float*)d_in[5];
    const float* bn   = (const float*)d_in[6];
    const float* Wo   = (const float*)d_in[7];
    const float* bo   = (const float*)d_in[8];
    const float* Wr   = (const float*)d_in[9];
    const float* lng  = (const float*)d_in[10];
    const float* lnb  = (const float*)d_in[11];
    const float* flng = (const float*)d_in[12];
    const float* flnb = (const float*)d_in[13];
    const float* linw = (const float*)d_in[14];
    const float* bias = (const float*)d_in[15];
    float* out = (float*)d_out;

    cudaFuncSetAttribute(fused_kernel,
                         cudaFuncAttributeMaxDynamicSharedMemorySize, FUSED_SMEM);

    detect_kernel<<<1, 32>>>((const unsigned int*)ei, (const unsigned int*)mk);
    zero_all_kernel<<<1024, 256>>>();
    wprep_kernel<<<9, 512>>>(Wn, Wo, Wr);
    adj_build_kernel<<<N_EDGES / 256, 256>>>(ei, mk);
    aprep_kernel<<<NG, 256>>>();

    fused_kernel<<<NG, 512, FUSED_SMEM>>>(
        x, bn, bo, lng, lnb,
        s, flng, flnb, linw, bias, out);

    loss_kernel<<<1, 256>>>(Wo, bo, out);
}

// round 16
// speedup vs baseline: 1.3075x; 1.1093x over previous
#include <cuda_runtime.h>
#include <cuda_bf16.h>
#include <stdint.h>

// ---------------------------------------------------------------------------
// SEALNetwork fully fused: one CTA per graph runs all 3 GNN layers + pooling;
// h lives in shared memory throughout.
//   agg = (Ain.h).Wn^T + (Aout.h).Wo^T + cin (x) bn + cout (x) bo
// Adjacency = packed u8 counts (exact in bf16); bf16 hi/lo split elsewhere.
// R16: (1) LayerNorm computed directly from MMA accumulators via per-quad
// partial sums (kills the fp32 S round-trip: 64KB STS + 16K LDS + a phase
// per layer); (2) in/out-degrees computed as dp4a row-sums in aprep, so
// adj_build loses 1M atomics. Staging stays cp.async.bulk + mbarriers.
// ---------------------------------------------------------------------------

#define N_NODES 32768
#define N_EDGES 524288
#define NG      256
#define NPG     128
#define HD      128
#define NL      3
#define NC      16
#define BUFB    32768
#define ADJ_EL  (NG * NPG * NPG)

__device__ int           g_cin[N_NODES];
__device__ int           g_cout[N_NODES];
__device__ float         g_l1[NG];
__device__ unsigned char g_adj[2][ADJ_EL];        // [0]=masked(in), [1]=out
__device__ __align__(16) __nv_bfloat16 g_aimg[2][NG][16384];    // adj images
__device__ __align__(16) __nv_bfloat16 g_wimg[NL][3][2][16384]; // [l][m][hi/lo]
__device__ int           g_ei64;
__device__ int           g_mk_kind;               // 0=u8/bool 1=i32 2=f32

// ---------------------------------------------------------------------------
__device__ __forceinline__ uint32_t smem_u32(const void* p) {
    uint32_t a;
    asm("{ .reg .u64 t; cvta.to.shared.u64 t, %1; cvt.u32.u64 %0, t; }"
        : "=r"(a) : "l"(p));
    return a;
}

__device__ __forceinline__ void ldm_x4(uint32_t& r0, uint32_t& r1,
                                       uint32_t& r2, uint32_t& r3,
                                       uint32_t addr) {
    asm volatile("ldmatrix.sync.aligned.m8n8.x4.shared.b16 {%0,%1,%2,%3}, [%4];"
                 : "=r"(r0), "=r"(r1), "=r"(r2), "=r"(r3) : "r"(addr));
}

__device__ __forceinline__ void ldm_x4t(uint32_t& r0, uint32_t& r1,
                                        uint32_t& r2, uint32_t& r3,
                                        uint32_t addr) {
    asm volatile(
        "ldmatrix.sync.aligned.m8n8.x4.trans.shared.b16 {%0,%1,%2,%3}, [%4];"
        : "=r"(r0), "=r"(r1), "=r"(r2), "=r"(r3) : "r"(addr));
}

__device__ __forceinline__ void mma_bf16(float* c, const uint32_t* a,
                                         uint32_t b0, uint32_t b1) {
    asm volatile(
        "mma.sync.aligned.m16n8k16.row.col.f32.bf16.bf16.f32 "
        "{%0,%1,%2,%3}, {%4,%5,%6,%7}, {%8,%9}, {%0,%1,%2,%3};"
        : "+f"(c[0]), "+f"(c[1]), "+f"(c[2]), "+f"(c[3])
        : "r"(a[0]), "r"(a[1]), "r"(a[2]), "r"(a[3]), "r"(b0), "r"(b1));
}

__device__ __forceinline__ uint32_t bf2pack(float a, float b) {
    unsigned short lo = __bfloat16_as_ushort(__float2bfloat16(a));
    unsigned short hi = __bfloat16_as_ushort(__float2bfloat16(b));
    return (uint32_t)lo | ((uint32_t)hi << 16);
}

__device__ __forceinline__ uint32_t swz(int r, int c) {
    return (uint32_t)(r * 256 + ((((c >> 3) ^ (r & 7)) << 4) | ((c & 7) * 2)));
}

// ---- mbarrier + bulk-DMA helpers ----
__device__ __forceinline__ void mbar_init(uint32_t a) {
    asm volatile("mbarrier.init.shared.b64 [%0], 1;" :: "r"(a) : "memory");
}
__device__ __forceinline__ void mbar_expect(uint32_t a, uint32_t bytes) {
    asm volatile("mbarrier.arrive.expect_tx.shared.b64 _, [%0], %1;"
                 :: "r"(a), "r"(bytes) : "memory");
}
__device__ __forceinline__ void mbar_wait(uint32_t a, uint32_t parity) {
    asm volatile(
        "{\n\t.reg .pred P;\n"
        "W%=:\n\t"
        "mbarrier.try_wait.parity.shared::cta.b64 P, [%0], %1;\n\t"
        "@!P bra W%=;\n\t}"
        :: "r"(a), "r"(parity) : "memory");
}
__device__ __forceinline__ void bulk_g2s(uint32_t dst, const void* src,
                                         uint32_t bytes, uint32_t mbar) {
    asm volatile(
        "cp.async.bulk.shared::cta.global.mbarrier::complete_tx::bytes "
        "[%0], [%1], %2, [%3];"
        :: "r"(dst), "l"(src), "r"(bytes), "r"(mbar) : "memory");
}

// Fused 3-term split GEMM: acc += A0*B0^T + A0*B1^T + A1*B0^T.
__device__ __forceinline__ void pass3_nn(float acc[2][4][4],
                                         uint32_t A0b, uint32_t A1b,
                                         uint32_t B0b, uint32_t B1b,
                                         int m_blk, int n_blk, int lane) {
    int ar = lane & 15, ak = lane >> 4;
    int br = (lane & 7) + ((lane & 16) >> 1), bk = (lane & 8) >> 3;
    #pragma unroll
    for (int ks = 0; ks < 8; ks++) {
        uint32_t a0[2][4], a1[2][4];
        #pragma unroll
        for (int mt = 0; mt < 2; mt++) {
            int row = m_blk + mt * 16 + ar;
            uint32_t off = (uint32_t)(row * 256 + (((ks * 2 + ak) ^ (row & 7)) << 4));
            ldm_x4(a0[mt][0], a0[mt][1], a0[mt][2], a0[mt][3], A0b + off);
            ldm_x4(a1[mt][0], a1[mt][1], a1[mt][2], a1[mt][3], A1b + off);
        }
        uint32_t b0[4][2], b1[4][2];
        #pragma unroll
        for (int np = 0; np < 2; np++) {
            int row = n_blk + np * 16 + br;
            uint32_t off = (uint32_t)(row * 256 + (((ks * 2 + bk) ^ (row & 7)) << 4));
            uint32_t r0, r1, r2, r3;
            ldm_x4(r0, r1, r2, r3, B0b + off);
            b0[np * 2][0] = r0;     b0[np * 2][1] = r1;
            b0[np * 2 + 1][0] = r2; b0[np * 2 + 1][1] = r3;
            ldm_x4(r0, r1, r2, r3, B1b + off);
            b1[np * 2][0] = r0;     b1[np * 2][1] = r1;
            b1[np * 2 + 1][0] = r2; b1[np * 2 + 1][1] = r3;
        }
        #pragma unroll
        for (int mt = 0; mt < 2; mt++)
            #pragma unroll
            for (int nt = 0; nt < 4; nt++) {
                mma_bf16(acc[mt][nt], a0[mt], b0[nt][0], b0[nt][1]);
                mma_bf16(acc[mt][nt], a0[mt], b1[nt][0], b1[nt][1]);
                mma_bf16(acc[mt][nt], a1[mt], b0[nt][0], b0[nt][1]);
            }
    }
}

// Fused 2-term adjacency GEMM: acc += C*(B0 + B1), B row-major (trans).
__device__ __forceinline__ void pass2_nt(float acc[2][4][4], uint32_t Cb,
                                         uint32_t B0b, uint32_t B1b,
                                         int m_blk, int n_blk, int lane) {
    int ar = lane & 15, ak = lane >> 4;
    int tr = lane & 15, tn = lane >> 4;
    #pragma unroll
    for (int ks = 0; ks < 8; ks++) {
        uint32_t c[2][4];
        #pragma unroll
        for (int mt = 0; mt < 2; mt++) {
            int row = m_blk + mt * 16 + ar;
            uint32_t off = (uint32_t)(row * 256 + (((ks * 2 + ak) ^ (row & 7)) << 4));
            ldm_x4(c[mt][0], c[mt][1], c[mt][2], c[mt][3], Cb + off);
        }
        uint32_t p[4][2], q[4][2];
        #pragma unroll
        for (int np = 0; np < 2; np++) {
            int row = ks * 16 + tr;
            int ng = ((n_blk + np * 16) >> 3) + tn;
            uint32_t off = (uint32_t)(row * 256 + ((ng ^ (row & 7)) << 4));
            uint32_t r0, r1, r2, r3;
            ldm_x4t(r0, r1, r2, r3, B0b + off);
            p[np * 2][0] = r0;     p[np * 2][1] = r1;
            p[np * 2 + 1][0] = r2; p[np * 2 + 1][1] = r3;
            ldm_x4t(r0, r1, r2, r3, B1b + off);
            q[np * 2][0] = r0;     q[np * 2][1] = r1;
            q[np * 2 + 1][0] = r2; q[np * 2 + 1][1] = r3;
        }
        #pragma unroll
        for (int mt = 0; mt < 2; mt++)
            #pragma unroll
            for (int nt = 0; nt < 4; nt++) {
                mma_bf16(acc[mt][nt], c[mt], p[nt][0], p[nt][1]);
                mma_bf16(acc[mt][nt], c[mt], q[nt][0], q[nt][1]);
            }
    }
}

// ---------------------------------------------------------------------------
__global__ void detect_kernel(const unsigned int* __restrict__ ei_w,
                              const unsigned int* __restrict__ mk_w) {
    int lane = threadIdx.x;
    int odd = 0;
    for (int i = lane; i < 64; i += 32)
        if (ei_w[2 * i + 1] != 0u) odd = 1;
    unsigned m1 = __ballot_sync(0xffffffffu, odd);
    int f1 = 0, mb = 0;
    for (int i = lane; i < 256; i += 32) {
        unsigned w = mk_w[i];
        if (w == 0x3F800000u) f1 = 1;
        else if ((w >> 8) != 0u) mb = 1;
    }
    unsigned mf = __ballot_sync(0xffffffffu, f1);
    unsigned mm = __ballot_sync(0xffffffffu, mb);
    if (lane == 0) {
        g_ei64 = (m1 == 0u) ? 1 : 0;
        g_mk_kind = mf ? 2 : (mm ? 0 : 1);
    }
}

__device__ __forceinline__ int load_idx(const void* ei, int pos) {
    if (g_ei64) return (int)((const long long*)ei)[pos];
    return ((const int*)ei)[pos];
}
__device__ __forceinline__ bool load_mask(const void* mk, int e) {
    int kind = g_mk_kind;
    if (kind == 0) return ((const unsigned char*)mk)[e] != 0;
    if (kind == 1) return ((const int*)mk)[e] != 0;
    return ((const float*)mk)[e] != 0.0f;
}

__global__ void zero_all_kernel() {
    int stride = gridDim.x * blockDim.x;
    int i0 = blockIdx.x * blockDim.x + threadIdx.x;
    uint4 z = make_uint4(0, 0, 0, 0);
    for (int i = i0; i < ADJ_EL / 16; i += stride) {
        ((uint4*)g_adj[0])[i] = z;
        ((uint4*)g_adj[1])[i] = z;
    }
}

__global__ void adj_build_kernel(const void* __restrict__ ei,
                                 const void* __restrict__ mk) {
    int e = blockIdx.x * blockDim.x + threadIdx.x;
    if (e >= N_EDGES) return;
    int t = load_idx(ei, N_EDGES + e);
    int s = load_idx(ei, e);
    if ((unsigned)t >= (unsigned)N_NODES) return;
    if ((unsigned)s >= (unsigned)N_NODES) return;
    if ((t >> 7) != (s >> 7)) return;
    int sel = load_mask(mk, e) ? 0 : 1;
    int idx = ((t >> 7) * NPG + (t & 127)) * NPG + (s & 127);
    atomicAdd(&((unsigned int*)g_adj[sel])[idx >> 2], 1u << ((idx & 3) * 8));
}

// adjacency u8 -> bf16 pre-swizzled image + degree row-sums. 1 block/graph.
__global__ void aprep_kernel() {
    __shared__ int rs[NPG];
    int g = blockIdx.x, tid = threadIdx.x;
    #pragma unroll
    for (int sel = 0; sel < 2; sel++) {
        if (tid < NPG) rs[tid] = 0;
        __syncthreads();
        const unsigned char* src = g_adj[sel] + (size_t)g * NPG * NPG;
        char* dst = (char*)g_aimg[sel][g];
        #pragma unroll
        for (int i = 0; i < 8; i++) {
            int gid = tid + i * 256;
            int r = gid >> 4, gq = gid & 15;
            uint2 raw = *(const uint2*)(src + r * NPG + gq * 8);
            uint32_t p[4];
            p[0] = bf2pack((float)(raw.x & 255), (float)((raw.x >> 8) & 255));
            p[1] = bf2pack((float)((raw.x >> 16) & 255), (float)(raw.x >> 24));
            p[2] = bf2pack((float)(raw.y & 255), (float)((raw.y >> 8) & 255));
            p[3] = bf2pack((float)((raw.y >> 16) & 255), (float)(raw.y >> 24));
            uint32_t off = (uint32_t)(r * 256 + ((gq ^ (r & 7)) << 4));
            *(uint4*)(dst + off) = make_uint4(p[0], p[1], p[2], p[3]);
            int bsum = __dp4a(raw.x, 0x01010101u,
                              __dp4a(raw.y, 0x01010101u, 0u));
            atomicAdd(&rs[r], bsum);
        }
        __syncthreads();
        if (tid < NPG)
            (sel ? g_cout : g_cin)[g * NPG + tid] = rs[tid];
        __syncthreads();
    }
}

// pre-split all 9 weight matrices into hi/lo smem-images. 1 block/matrix.
__global__ void wprep_kernel(const float* __restrict__ Wn_,
                             const float* __restrict__ Wo_,
                             const float* __restrict__ Wr_) {
    int idx = blockIdx.x;              // 0..8
    int l = idx / 3, m = idx % 3;
    const float* src = ((m == 0) ? Wn_ : (m == 1) ? Wo_ : Wr_) + l * HD * HD;
    char* hiI = (char*)g_wimg[l][m][0];
    char* loI = (char*)g_wimg[l][m][1];
    int tid = threadIdx.x;
    #pragma unroll
    for (int i = 0; i < 4; i++) {
        int gid = tid + i * 512;
        int r = gid >> 4, gq = gid & 15;
        const float* s8 = src + (size_t)r * HD + gq * 8;
        float v[8];
        *(float4*)(v)     = *(const float4*)(s8);
        *(float4*)(v + 4) = *(const float4*)(s8 + 4);
        uint32_t hi[4], lo[4];
        #pragma unroll
        for (int j = 0; j < 4; j++) {
            float a = v[2 * j], b = v[2 * j + 1];
            __nv_bfloat16 ha = __float2bfloat16(a), hb = __float2bfloat16(b);
            hi[j] = (uint32_t)__bfloat16_as_ushort(ha)
                  | ((uint32_t)__bfloat16_as_ushort(hb) << 16);
            lo[j] = bf2pack(a - __bfloat162float(ha), b - __bfloat162float(hb));
        }
        uint32_t off = (uint32_t)(r * 256 + ((gq ^ (r & 7)) << 4));
        *(uint4*)(hiI + off) = make_uint4(hi[0], hi[1], hi[2], hi[3]);
        *(uint4*)(loI + off) = make_uint4(lo[0], lo[1], lo[2], lo[3]);
    }
}

// ---------------------------------------------------------------------------
#define FUSED_SMEM (7 * BUFB)

__global__ void __launch_bounds__(512)
fused_kernel(const float* __restrict__ x,
             const float* __restrict__ bn_, const float* __restrict__ bo_,
             const float* __restrict__ lng_, const float* __restrict__ lnb_,
             const float* __restrict__ sIn,
             const float* __restrict__ flng, const float* __restrict__ flnb,
             const float* __restrict__ linw, const float* __restrict__ bias,
             float* __restrict__ dout) {
    extern __shared__ __align__(16) char dyn[];
    __shared__ float sbn[HD], sbo[HD], sgm[HD], sbt[HD];
    __shared__ float colsum[NC], xcs[NC];
    __shared__ __align__(8) unsigned long long mbars[3];

    int tid = threadIdx.x;
    int w = tid >> 5, lane = tid & 31;
    int m_blk = (w >> 2) * 32, n_blk = (w & 3) * 32;
    int grp = lane >> 2, tig = lane & 3;
    int g = blockIdx.x, row0 = g * 128;

    uint32_t base = smem_u32(dyn);
    uint32_t C0 = base, C1 = base + BUFB, Dd = base + 2 * BUFB;
    uint32_t A0 = base + 3 * BUFB, A1 = base + 4 * BUFB;
    uint32_t W0 = base + 5 * BUFB, W1 = base + 6 * BUFB;
    float* P  = (float*)(dyn + 3 * BUFB);
    float* PS = (float*)dyn;            // [128][4] LN partial sums (C0 region)
    float* PQ = (float*)(dyn + 2048);   // [128][4] LN partial sumsq

    uint32_t mbA = smem_u32(&mbars[0]);
    uint32_t mbB = smem_u32(&mbars[1]);
    uint32_t mbC = smem_u32(&mbars[2]);

    if (tid == 0) { mbar_init(mbA); mbar_init(mbB); mbar_init(mbC); }
    __syncthreads();

    int pa = 0, pb = 0, pc = 0;

    // issue layer-0 staging (adj + Wr) — overlaps the x-split below
    if (tid == 0) {
        mbar_expect(mbA, 4 * BUFB);
        bulk_g2s(C0, g_aimg[0][g], BUFB, mbA);
        bulk_g2s(C1, g_aimg[1][g], BUFB, mbA);
        bulk_g2s(W0, g_wimg[0][2][0], BUFB, mbA);
        bulk_g2s(W1, g_wimg[0][2][1], BUFB, mbA);
    }

    // --- layer-0 h: split x into A0/A1 ---
    #pragma unroll
    for (int i = 0; i < 4; i++) {
        int gid = tid + i * 512;
        int r = gid >> 4, gq = gid & 15;
        const float* src = x + (size_t)(row0 + r) * HD + gq * 8;
        float v[8];
        *(float4*)(v)     = *(const float4*)(src);
        *(float4*)(v + 4) = *(const float4*)(src + 4);
        uint32_t hi[4], lo[4];
        #pragma unroll
        for (int j = 0; j < 4; j++) {
            float a = v[2 * j], b = v[2 * j + 1];
            __nv_bfloat16 ha = __float2bfloat16(a), hb = __float2bfloat16(b);
            hi[j] = (uint32_t)__bfloat16_as_ushort(ha)
                  | ((uint32_t)__bfloat16_as_ushort(hb) << 16);
            lo[j] = bf2pack(a - __bfloat162float(ha), b - __bfloat162float(hb));
        }
        uint32_t off = (uint32_t)(r * 256 + ((gq ^ (r & 7)) << 4));
        *(uint4*)((char*)dyn + (A0 - base) + off) = make_uint4(hi[0], hi[1], hi[2], hi[3]);
        *(uint4*)((char*)dyn + (A1 - base) + off) = make_uint4(lo[0], lo[1], lo[2], lo[3]);
    }

    #pragma unroll 1
    for (int l = 0; l < NL; l++) {
        mbar_wait(mbA, (uint32_t)(pa & 1)); pa++;   // adj + Wr(l) ready
        if (tid < HD) {
            sbn[tid] = bn_[l * HD + tid];
            sbo[tid] = bo_[l * HD + tid];
            sgm[tid] = lng_[l * HD + tid];
            sbt[tid] = lnb_[l * HD + tid];
        }
        __syncthreads();   // x-split / LN writes visible; params loaded

        // root = h @ Wr^T (fused 3-term)
        float root[2][4][4];
        #pragma unroll
        for (int mt = 0; mt < 2; mt++)
            #pragma unroll
            for (int nt = 0; nt < 4; nt++)
                #pragma unroll
                for (int q = 0; q < 4; q++) root[mt][nt][q] = 0.f;
        pass3_nn(root, A0, A1, W0, W1, m_blk, n_blk, lane);
        __syncthreads();   // all warps done reading W0/W1
        if (tid == 0) {    // prefetch Wn -> W0/W1 (overlaps both adj passes)
            mbar_expect(mbB, 2 * BUFB);
            bulk_g2s(W0, g_wimg[l][0][0], BUFB, mbB);
            bulk_g2s(W1, g_wimg[l][0][1], BUFB, mbB);
        }

        // Hin = Ain @ (A0 + A1)
        float hacc[2][4][4];
        #pragma unroll
        for (int mt = 0; mt < 2; mt++)
            #pragma unroll
            for (int nt = 0; nt < 4; nt++)
                #pragma unroll
                for (int q = 0; q < 4; q++) hacc[mt][nt][q] = 0.f;
        pass2_nt(hacc, C0, A0, A1, m_blk, n_blk, lane);
        __syncthreads();   // all done reading C0 before overwrite
        #pragma unroll
        for (int mt = 0; mt < 2; mt++) {
            #pragma unroll
            for (int nt = 0; nt < 4; nt++) {
                int rg = m_blk + mt * 16 + grp;
                int cg = n_blk + nt * 8 + tig * 2;
                #pragma unroll
                for (int half = 0; half < 2; half++) {
                    int row = rg + half * 8;
                    float a = hacc[mt][nt][half * 2], b = hacc[mt][nt][half * 2 + 1];
                    __nv_bfloat16 ha = __float2bfloat16(a), hb = __float2bfloat16(b);
                    uint32_t off = swz(row, cg);
                    *(uint32_t*)((char*)dyn + (C0 - base) + off) =
                        (uint32_t)__bfloat16_as_ushort(ha)
                        | ((uint32_t)__bfloat16_as_ushort(hb) << 16);
                    *(uint32_t*)((char*)dyn + (Dd - base) + off) =
                        bf2pack(a - __bfloat162float(ha), b - __bfloat162float(hb));
                }
            }
        }

        // Hout = Aout @ (A0 + A1)
        #pragma unroll
        for (int mt = 0; mt < 2; mt++)
            #pragma unroll
            for (int nt = 0; nt < 4; nt++)
                #pragma unroll
                for (int q = 0; q < 4; q++) hacc[mt][nt][q] = 0.f;
        pass2_nt(hacc, C1, A0, A1, m_blk, n_blk, lane);
        __syncthreads();   // all done reading C1 + A0/A1 (h)
        if (tid == 0) {    // prefetch Wo-hi -> A0 (h-hi now dead)
            mbar_expect(mbC, BUFB);
            bulk_g2s(A0, g_wimg[l][1][0], BUFB, mbC);
        }
        #pragma unroll
        for (int mt = 0; mt < 2; mt++) {
            #pragma unroll
            for (int nt = 0; nt < 4; nt++) {
                int rg = m_blk + mt * 16 + grp;
                int cg = n_blk + nt * 8 + tig * 2;
                #pragma unroll
                for (int half = 0; half < 2; half++) {
                    int row = rg + half * 8;
                    float a = hacc[mt][nt][half * 2], b = hacc[mt][nt][half * 2 + 1];
                    __nv_bfloat16 ha = __float2bfloat16(a), hb = __float2bfloat16(b);
                    uint32_t off = swz(row, cg);
                    *(uint32_t*)((char*)dyn + (C1 - base) + off) =
                        (uint32_t)__bfloat16_as_ushort(ha)
                        | ((uint32_t)__bfloat16_as_ushort(hb) << 16);
                    *(uint32_t*)((char*)dyn + (A1 - base) + off) =
                        bf2pack(a - __bfloat162float(ha), b - __bfloat162float(hb));
                }
            }
        }
        __syncthreads();   // Hin/Hout stores visible
        mbar_wait(mbB, (uint32_t)(pb & 1)); pb++;   // Wn ready

        // agg = Hin @ Wn^T
        float agg[2][4][4];
        #pragma unroll
        for (int mt = 0; mt < 2; mt++)
            #pragma unroll
            for (int nt = 0; nt < 4; nt++)
                #pragma unroll
                for (int q = 0; q < 4; q++) agg[mt][nt][q] = 0.f;
        pass3_nn(agg, C0, Dd, W0, W1, m_blk, n_blk, lane);
        __syncthreads();   // done reading W1 (Wn-lo)
        if (tid == 0) {    // Wo-lo -> W1
            mbar_expect(mbA, BUFB);
            bulk_g2s(W1, g_wimg[l][1][1], BUFB, mbA);
        }
        mbar_wait(mbC, (uint32_t)(pc & 1)); pc++;   // Wo-hi in A0
        mbar_wait(mbA, (uint32_t)(pa & 1)); pa++;   // Wo-lo in W1

        // agg += Hout @ Wo^T  (Hhi=C1, Hlo=A1, Whi=A0, Wlo=W1)
        pass3_nn(agg, C1, A1, A0, W1, m_blk, n_blk, lane);
        __syncthreads();   // before partials overwrite C0 region

        // ---- epilogue + LN partials, direct from accumulators ----
        #pragma unroll
        for (int mt = 0; mt < 2; mt++) {
            #pragma unroll
            for (int half = 0; half < 2; half++) {
                int row = m_blk + mt * 16 + grp + half * 8;
                float ci = (float)g_cin[row0 + row];
                float co = (float)g_cout[row0 + row];
                float inv = 1.0f / fmaxf(ci + co, 1.0f);
                float ls = 0.f, lq = 0.f;
                #pragma unroll
                for (int nt = 0; nt < 4; nt++) {
                    int cg = n_blk + nt * 8 + tig * 2;
                    float v0 = (agg[mt][nt][half * 2]     + ci * sbn[cg]
                                + co * sbo[cg]) * inv + root[mt][nt][half * 2];
                    float v1 = (agg[mt][nt][half * 2 + 1] + ci * sbn[cg + 1]
                                + co * sbo[cg + 1]) * inv + root[mt][nt][half * 2 + 1];
                    agg[mt][nt][half * 2]     = v0;
                    agg[mt][nt][half * 2 + 1] = v1;
                    ls += v0 + v1;
                    lq += v0 * v0 + v1 * v1;
                }
                ls += __shfl_xor_sync(0xffffffffu, ls, 1);
                ls += __shfl_xor_sync(0xffffffffu, ls, 2);
                lq += __shfl_xor_sync(0xffffffffu, lq, 1);
                lq += __shfl_xor_sync(0xffffffffu, lq, 2);
                if (tig == 0) {
                    PS[row * 4 + (w & 3)] = ls;
                    PQ[row * 4 + (w & 3)] = lq;
                }
            }
        }
        __syncthreads();

        // ---- normalize + ReLU from registers; write next h or final P ----
        #pragma unroll
        for (int mt = 0; mt < 2; mt++) {
            #pragma unroll
            for (int half = 0; half < 2; half++) {
                int row = m_blk + mt * 16 + grp + half * 8;
                float sum = PS[row * 4 + 0] + PS[row * 4 + 1]
                          + PS[row * 4 + 2] + PS[row * 4 + 3];
                float sq  = PQ[row * 4 + 0] + PQ[row * 4 + 1]
                          + PQ[row * 4 + 2] + PQ[row * 4 + 3];
                float mu   = sum * (1.0f / 128.0f);
                float var  = sq * (1.0f / 128.0f) - mu * mu;
                float rstd = rsqrtf(var + 1e-5f);
                #pragma unroll
                for (int nt = 0; nt < 4; nt++) {
                    int cg = n_blk + nt * 8 + tig * 2;
                    float o0 = fmaxf((agg[mt][nt][half * 2]     - mu) * rstd
                                     * sgm[cg]     + sbt[cg],     0.f);
                    float o1 = fmaxf((agg[mt][nt][half * 2 + 1] - mu) * rstd
                                     * sgm[cg + 1] + sbt[cg + 1], 0.f);
                    if (l < NL - 1) {
                        uint32_t off = swz(row, cg);
                        __nv_bfloat16 h0 = __float2bfloat16(o0);
                        __nv_bfloat16 h1 = __float2bfloat16(o1);
                        *(uint32_t*)((char*)dyn + (A0 - base) + off) =
                            (uint32_t)__bfloat16_as_ushort(h0)
                            | ((uint32_t)__bfloat16_as_ushort(h1) << 16);
                        *(uint32_t*)((char*)dyn + (A1 - base) + off) =
                            bf2pack(o0 - __bfloat162float(h0),
                                    o1 - __bfloat162float(h1));
                    } else {
                        *(float2*)(P + row * 132 + cg) = make_float2(o0, o1);
                    }
                }
            }
        }

        if (l < NL - 1) {
            __syncthreads();   // partial reads done; C0/C1/W0/W1 free
            if (tid == 0) {    // next-layer adj + Wr
                mbar_expect(mbA, 4 * BUFB);
                bulk_g2s(C0, g_aimg[0][g], BUFB, mbA);
                bulk_g2s(C1, g_aimg[1][g], BUFB, mbA);
                bulk_g2s(W0, g_wimg[l + 1][2][0], BUFB, mbA);
                bulk_g2s(W1, g_wimg[l + 1][2][1], BUFB, mbA);
            }
        }
    }

    // =================== pooling head (in-CTA) ===================
    __syncthreads();
    float* sdP = (float*)dyn;
    float* plP = (float*)(dyn + 8192);

    *(float4*)(sdP + tid * 4) =
        *(const float4*)(sIn + (size_t)g * NPG * NC + tid * 4);
    __syncthreads();

    if (tid < NC) {
        float cs = 0.f;
        for (int n = 0; n < NPG; n++) cs += sdP[n * NC + tid];
        colsum[tid] = cs;
    }

    {
        int hcol = tid & 127, cgrp = tid >> 7;
        float pacc[4] = {0.f, 0.f, 0.f, 0.f};
        #pragma unroll 4
        for (int n = 0; n < NPG; n++) {
            float xv = P[n * 132 + hcol];
            #pragma unroll
            for (int c = 0; c < 4; c++)
                pacc[c] = fmaf(sdP[n * NC + cgrp * 4 + c], xv, pacc[c]);
        }
        #pragma unroll
        for (int c = 0; c < 4; c++)
            plP[(cgrp * 4 + c) * 128 + hcol] = pacc[c];
    }
    __syncthreads();

    {
        int rr = w;
        float4 v = *(float4*)(plP + rr * 128 + lane * 4);
        float sum = v.x + v.y + v.z + v.w;
        float sq  = v.x * v.x + v.y * v.y + v.z * v.z + v.w * v.w;
        #pragma unroll
        for (int o = 16; o; o >>= 1) {
            sum += __shfl_xor_sync(0xffffffffu, sum, o);
            sq  += __shfl_xor_sync(0xffffffffu, sq,  o);
        }
        float mu   = sum * (1.0f / 128.0f);
        float var  = sq * (1.0f / 128.0f) - mu * mu;
        float rstd = rsqrtf(var + 1e-5f);
        int f = lane * 4;
        float dot = ((v.x - mu) * rstd * flng[f + 0] + flnb[f + 0]) * linw[f + 0]
                  + ((v.y - mu) * rstd * flng[f + 1] + flnb[f + 1]) * linw[f + 1]
                  + ((v.z - mu) * rstd * flng[f + 2] + flnb[f + 2]) * linw[f + 2]
                  + ((v.w - mu) * rstd * flng[f + 3] + flnb[f + 3]) * linw[f + 3];
        #pragma unroll
        for (int o = 16; o; o >>= 1) dot += __shfl_xor_sync(0xffffffffu, dot, o);
        if (lane == 0) xcs[rr] = dot;
    }
    __syncthreads();

    if (tid == 0) {
        float ov = 0.f, l1 = 0.f, dn = 0.f;
        #pragma unroll
        for (int c = 0; c < NC; c++) {
            float mflag = (colsum[c] > 0.f) ? 1.f : 0.f;
            float v = xcs[c] * mflag;
            dout[257 + g * NC + c] = v;
            ov += v;
            l1 += fabsf(v);
            dn += mflag;
        }
        dout[g] = ov + bias[0];
        g_l1[g] = l1 / (dn + 1e-7f);
    }
}

// losses = 0.01*(sum|Wo|+sum|bo|) + 0.01*mean_g(l1[g])
__global__ void loss_kernel(const float* __restrict__ Wo,
                            const float* __restrict__ bo,
                            float* __restrict__ dout) {
    __shared__ float red[256];
    __shared__ float sreg;
    int tid = threadIdx.x;
    float rs = 0.f;
    for (int i = tid; i < NL * HD * HD; i += 256) rs += fabsf(Wo[i]);
    for (int i = tid; i < NL * HD; i += 256)      rs += fabsf(bo[i]);
    red[tid] = rs;
    __syncthreads();
    for (int o = 128; o; o >>= 1) {
        if (tid < o) red[tid] += red[tid + o];
        __syncthreads();
    }
    if (tid == 0) sreg = red[0];
    __syncthreads();
    float ls = (tid < NG) ? g_l1[tid] : 0.f;
    red[tid] = ls;
    __syncthreads();
    for (int o = 128; o; o >>= 1) {
        if (tid < o) red[tid] += red[tid + o];
        __syncthreads();
    }
    if (tid == 0)
        dout[256] = 0.01f * sreg + 0.01f * (red[0] / (float)NG);
}

// ---------------------------------------------------------------------------
extern "C" void kernel_launch(void* const* d_in, const int* in_sizes, int n_in,
                              void* d_out, int out_size) {
    const float* x    = (const float*)d_in[0];
    const void*  ei   = d_in[1];
    const void*  mk   = d_in[2];
    const float* s    = (const float*)d_in[3];
    const float* Wn   = (const float*)d_in[5];
    const float* bn   = (const float*)d_in[6];
    const float* Wo   = (const float*)d_in[7];
    const float* bo   = (const float*)d_in[8];
    const float* Wr   = (const float*)d_in[9];
    const float* lng  = (const float*)d_in[10];
    const float* lnb  = (const float*)d_in[11];
    const float* flng = (const float*)d_in[12];
    const float* flnb = (const float*)d_in[13];
    const float* linw = (const float*)d_in[14];
    const float* bias = (const float*)d_in[15];
    float* out = (float*)d_out;

    cudaFuncSetAttribute(fused_kernel,
                         cudaFuncAttributeMaxDynamicSharedMemorySize, FUSED_SMEM);

    detect_kernel<<<1, 32>>>((const unsigned int*)ei, (const unsigned int*)mk);
    zero_all_kernel<<<1024, 256>>>();
    wprep_kernel<<<9, 512>>>(Wn, Wo, Wr);
    adj_build_kernel<<<N_EDGES / 256, 256>>>(ei, mk);
    aprep_kernel<<<NG, 256>>>();

    fused_kernel<<<NG, 512, FUSED_SMEM>>>(
        x, bn, bo, lng, lnb,
        s, flng, flnb, linw, bias, out);

    loss_kernel<<<1, 256>>>(Wo, bo, out);
}

// round 17
// speedup vs baseline: 1.3286x; 1.0162x over previous
#include <cuda_runtime.h>
#include <cuda_bf16.h>
#include <stdint.h>

// ---------------------------------------------------------------------------
// SEALNetwork fully fused: one CTA per graph runs all 3 GNN layers + pooling;
// h lives in shared memory throughout.
//   agg = (Ain.h).Wn^T + (Aout.h).Wo^T + cin (x) bn + cout (x) bo
// Adjacency = packed u8 counts (exact in bf16); bf16 hi/lo split elsewhere.
// R17: prologue compression — detect+zero+wprep merged into ONE prep kernel
// (6 launches -> 5); adj_build processes 4 edges/thread (coalesced index
// loads, 4 atomics in flight: it was atomic-latency-bound at issue=11.6%).
// Fused kernel unchanged from R16 (validated).
// ---------------------------------------------------------------------------

#define N_NODES 32768
#define N_EDGES 524288
#define NG      256
#define NPG     128
#define HD      128
#define NL      3
#define NC      16
#define BUFB    32768
#define ADJ_EL  (NG * NPG * NPG)

__device__ int           g_cin[N_NODES];
__device__ int           g_cout[N_NODES];
__device__ float         g_l1[NG];
__device__ unsigned char g_adj[2][ADJ_EL];        // [0]=masked(in), [1]=out
__device__ __align__(16) __nv_bfloat16 g_aimg[2][NG][16384];    // adj images
__device__ __align__(16) __nv_bfloat16 g_wimg[NL][3][2][16384]; // [l][m][hi/lo]
__device__ int           g_ei64;
__device__ int           g_mk_kind;               // 0=u8/bool 1=i32 2=f32

// ---------------------------------------------------------------------------
__device__ __forceinline__ uint32_t smem_u32(const void* p) {
    uint32_t a;
    asm("{ .reg .u64 t; cvta.to.shared.u64 t, %1; cvt.u32.u64 %0, t; }"
        : "=r"(a) : "l"(p));
    return a;
}

__device__ __forceinline__ void ldm_x4(uint32_t& r0, uint32_t& r1,
                                       uint32_t& r2, uint32_t& r3,
                                       uint32_t addr) {
    asm volatile("ldmatrix.sync.aligned.m8n8.x4.shared.b16 {%0,%1,%2,%3}, [%4];"
                 : "=r"(r0), "=r"(r1), "=r"(r2), "=r"(r3) : "r"(addr));
}

__device__ __forceinline__ void ldm_x4t(uint32_t& r0, uint32_t& r1,
                                        uint32_t& r2, uint32_t& r3,
                                        uint32_t addr) {
    asm volatile(
        "ldmatrix.sync.aligned.m8n8.x4.trans.shared.b16 {%0,%1,%2,%3}, [%4];"
        : "=r"(r0), "=r"(r1), "=r"(r2), "=r"(r3) : "r"(addr));
}

__device__ __forceinline__ void mma_bf16(float* c, const uint32_t* a,
                                         uint32_t b0, uint32_t b1) {
    asm volatile(
        "mma.sync.aligned.m16n8k16.row.col.f32.bf16.bf16.f32 "
        "{%0,%1,%2,%3}, {%4,%5,%6,%7}, {%8,%9}, {%0,%1,%2,%3};"
        : "+f"(c[0]), "+f"(c[1]), "+f"(c[2]), "+f"(c[3])
        : "r"(a[0]), "r"(a[1]), "r"(a[2]), "r"(a[3]), "r"(b0), "r"(b1));
}

__device__ __forceinline__ uint32_t bf2pack(float a, float b) {
    unsigned short lo = __bfloat16_as_ushort(__float2bfloat16(a));
    unsigned short hi = __bfloat16_as_ushort(__float2bfloat16(b));
    return (uint32_t)lo | ((uint32_t)hi << 16);
}

__device__ __forceinline__ uint32_t swz(int r, int c) {
    return (uint32_t)(r * 256 + ((((c >> 3) ^ (r & 7)) << 4) | ((c & 7) * 2)));
}

// ---- mbarrier + bulk-DMA helpers ----
__device__ __forceinline__ void mbar_init(uint32_t a) {
    asm volatile("mbarrier.init.shared.b64 [%0], 1;" :: "r"(a) : "memory");
}
__device__ __forceinline__ void mbar_expect(uint32_t a, uint32_t bytes) {
    asm volatile("mbarrier.arrive.expect_tx.shared.b64 _, [%0], %1;"
                 :: "r"(a), "r"(bytes) : "memory");
}
__device__ __forceinline__ void mbar_wait(uint32_t a, uint32_t parity) {
    asm volatile(
        "{\n\t.reg .pred P;\n"
        "W%=:\n\t"
        "mbarrier.try_wait.parity.shared::cta.b64 P, [%0], %1;\n\t"
        "@!P bra W%=;\n\t}"
        :: "r"(a), "r"(parity) : "memory");
}
__device__ __forceinline__ void bulk_g2s(uint32_t dst, const void* src,
                                         uint32_t bytes, uint32_t mbar) {
    asm volatile(
        "cp.async.bulk.shared::cta.global.mbarrier::complete_tx::bytes "
        "[%0], [%1], %2, [%3];"
        :: "r"(dst), "l"(src), "r"(bytes), "r"(mbar) : "memory");
}

// Fused 3-term split GEMM: acc += A0*B0^T + A0*B1^T + A1*B0^T.
__device__ __forceinline__ void pass3_nn(float acc[2][4][4],
                                         uint32_t A0b, uint32_t A1b,
                                         uint32_t B0b, uint32_t B1b,
                                         int m_blk, int n_blk, int lane) {
    int ar = lane & 15, ak = lane >> 4;
    int br = (lane & 7) + ((lane & 16) >> 1), bk = (lane & 8) >> 3;
    #pragma unroll
    for (int ks = 0; ks < 8; ks++) {
        uint32_t a0[2][4], a1[2][4];
        #pragma unroll
        for (int mt = 0; mt < 2; mt++) {
            int row = m_blk + mt * 16 + ar;
            uint32_t off = (uint32_t)(row * 256 + (((ks * 2 + ak) ^ (row & 7)) << 4));
            ldm_x4(a0[mt][0], a0[mt][1], a0[mt][2], a0[mt][3], A0b + off);
            ldm_x4(a1[mt][0], a1[mt][1], a1[mt][2], a1[mt][3], A1b + off);
        }
        uint32_t b0[4][2], b1[4][2];
        #pragma unroll
        for (int np = 0; np < 2; np++) {
            int row = n_blk + np * 16 + br;
            uint32_t off = (uint32_t)(row * 256 + (((ks * 2 + bk) ^ (row & 7)) << 4));
            uint32_t r0, r1, r2, r3;
            ldm_x4(r0, r1, r2, r3, B0b + off);
            b0[np * 2][0] = r0;     b0[np * 2][1] = r1;
            b0[np * 2 + 1][0] = r2; b0[np * 2 + 1][1] = r3;
            ldm_x4(r0, r1, r2, r3, B1b + off);
            b1[np * 2][0] = r0;     b1[np * 2][1] = r1;
            b1[np * 2 + 1][0] = r2; b1[np * 2 + 1][1] = r3;
        }
        #pragma unroll
        for (int mt = 0; mt < 2; mt++)
            #pragma unroll
            for (int nt = 0; nt < 4; nt++) {
                mma_bf16(acc[mt][nt], a0[mt], b0[nt][0], b0[nt][1]);
                mma_bf16(acc[mt][nt], a0[mt], b1[nt][0], b1[nt][1]);
                mma_bf16(acc[mt][nt], a1[mt], b0[nt][0], b0[nt][1]);
            }
    }
}

// Fused 2-term adjacency GEMM: acc += C*(B0 + B1), B row-major (trans).
__device__ __forceinline__ void pass2_nt(float acc[2][4][4], uint32_t Cb,
                                         uint32_t B0b, uint32_t B1b,
                                         int m_blk, int n_blk, int lane) {
    int ar = lane & 15, ak = lane >> 4;
    int tr = lane & 15, tn = lane >> 4;
    #pragma unroll
    for (int ks = 0; ks < 8; ks++) {
        uint32_t c[2][4];
        #pragma unroll
        for (int mt = 0; mt < 2; mt++) {
            int row = m_blk + mt * 16 + ar;
            uint32_t off = (uint32_t)(row * 256 + (((ks * 2 + ak) ^ (row & 7)) << 4));
            ldm_x4(c[mt][0], c[mt][1], c[mt][2], c[mt][3], Cb + off);
        }
        uint32_t p[4][2], q[4][2];
        #pragma unroll
        for (int np = 0; np < 2; np++) {
            int row = ks * 16 + tr;
            int ng = ((n_blk + np * 16) >> 3) + tn;
            uint32_t off = (uint32_t)(row * 256 + ((ng ^ (row & 7)) << 4));
            uint32_t r0, r1, r2, r3;
            ldm_x4t(r0, r1, r2, r3, B0b + off);
            p[np * 2][0] = r0;     p[np * 2][1] = r1;
            p[np * 2 + 1][0] = r2; p[np * 2 + 1][1] = r3;
            ldm_x4t(r0, r1, r2, r3, B1b + off);
            q[np * 2][0] = r0;     q[np * 2][1] = r1;
            q[np * 2 + 1][0] = r2; q[np * 2 + 1][1] = r3;
        }
        #pragma unroll
        for (int mt = 0; mt < 2; mt++)
            #pragma unroll
            for (int nt = 0; nt < 4; nt++) {
                mma_bf16(acc[mt][nt], c[mt], p[nt][0], p[nt][1]);
                mma_bf16(acc[mt][nt], c[mt], q[nt][0], q[nt][1]);
            }
    }
}

// ---------------------------------------------------------------------------
__device__ __forceinline__ int load_idx(const void* ei, int pos) {
    if (g_ei64) return (int)((const long long*)ei)[pos];
    return ((const int*)ei)[pos];
}
__device__ __forceinline__ bool load_mask(const void* mk, int e) {
    int kind = g_mk_kind;
    if (kind == 0) return ((const unsigned char*)mk)[e] != 0;
    if (kind == 1) return ((const int*)mk)[e] != 0;
    return ((const float*)mk)[e] != 0.0f;
}

// prep: blocks 0-8 split weights; block 9 detects dtypes; rest zero g_adj.
__global__ void prep_kernel(const float* __restrict__ Wn_,
                            const float* __restrict__ Wo_,
                            const float* __restrict__ Wr_,
                            const unsigned int* __restrict__ ei_w,
                            const unsigned int* __restrict__ mk_w) {
    int b = blockIdx.x, tid = threadIdx.x;
    if (b < 9) {
        int l = b / 3, m = b % 3;
        const float* src = ((m == 0) ? Wn_ : (m == 1) ? Wo_ : Wr_) + l * HD * HD;
        char* hiI = (char*)g_wimg[l][m][0];
        char* loI = (char*)g_wimg[l][m][1];
        #pragma unroll
        for (int i = 0; i < 8; i++) {
            int gid = tid + i * 256;
            int r = gid >> 4, gq = gid & 15;
            const float* s8 = src + (size_t)r * HD + gq * 8;
            float v[8];
            *(float4*)(v)     = *(const float4*)(s8);
            *(float4*)(v + 4) = *(const float4*)(s8 + 4);
            uint32_t hi[4], lo[4];
            #pragma unroll
            for (int j = 0; j < 4; j++) {
                float a = v[2 * j], bb = v[2 * j + 1];
                __nv_bfloat16 ha = __float2bfloat16(a), hb = __float2bfloat16(bb);
                hi[j] = (uint32_t)__bfloat16_as_ushort(ha)
                      | ((uint32_t)__bfloat16_as_ushort(hb) << 16);
                lo[j] = bf2pack(a - __bfloat162float(ha), bb - __bfloat162float(hb));
            }
            uint32_t off = (uint32_t)(r * 256 + ((gq ^ (r & 7)) << 4));
            *(uint4*)(hiI + off) = make_uint4(hi[0], hi[1], hi[2], hi[3]);
            *(uint4*)(loI + off) = make_uint4(lo[0], lo[1], lo[2], lo[3]);
        }
    } else if (b == 9) {
        if (tid < 32) {
            int lane = tid;
            int odd = 0;
            for (int i = lane; i < 64; i += 32)
                if (ei_w[2 * i + 1] != 0u) odd = 1;
            unsigned m1 = __ballot_sync(0xffffffffu, odd);
            int f1 = 0, mb = 0;
            for (int i = lane; i < 256; i += 32) {
                unsigned wv = mk_w[i];
                if (wv == 0x3F800000u) f1 = 1;
                else if ((wv >> 8) != 0u) mb = 1;
            }
            unsigned mf = __ballot_sync(0xffffffffu, f1);
            unsigned mm = __ballot_sync(0xffffffffu, mb);
            if (lane == 0) {
                g_ei64 = (m1 == 0u) ? 1 : 0;
                g_mk_kind = mf ? 2 : (mm ? 0 : 1);
            }
        }
    } else {
        int nz = gridDim.x - 10;
        int i0 = (b - 10) * 256 + tid;
        int stride = nz * 256;
        uint4 z = make_uint4(0, 0, 0, 0);
        for (int i = i0; i < ADJ_EL / 16; i += stride) {
            ((uint4*)g_adj[0])[i] = z;
            ((uint4*)g_adj[1])[i] = z;
        }
    }
}

// 4 edges/thread: coalesced index loads, 4 independent atomics in flight.
__global__ void adj_build_kernel(const void* __restrict__ ei,
                                 const void* __restrict__ mk) {
    int e0 = (blockIdx.x * blockDim.x + threadIdx.x) * 4;
    #pragma unroll
    for (int j = 0; j < 4; j++) {
        int e = e0 + j;
        if (e >= N_EDGES) break;
        int t = load_idx(ei, N_EDGES + e);
        int s = load_idx(ei, e);
        if ((unsigned)t >= (unsigned)N_NODES) continue;
        if ((unsigned)s >= (unsigned)N_NODES) continue;
        if ((t >> 7) != (s >> 7)) continue;
        int sel = load_mask(mk, e) ? 0 : 1;
        int idx = ((t >> 7) * NPG + (t & 127)) * NPG + (s & 127);
        atomicAdd(&((unsigned int*)g_adj[sel])[idx >> 2], 1u << ((idx & 3) * 8));
    }
}

// adjacency u8 -> bf16 pre-swizzled image + degree row-sums. 1 block/graph.
__global__ void aprep_kernel() {
    __shared__ int rs[NPG];
    int g = blockIdx.x, tid = threadIdx.x;
    #pragma unroll
    for (int sel = 0; sel < 2; sel++) {
        if (tid < NPG) rs[tid] = 0;
        __syncthreads();
        const unsigned char* src = g_adj[sel] + (size_t)g * NPG * NPG;
        char* dst = (char*)g_aimg[sel][g];
        #pragma unroll
        for (int i = 0; i < 8; i++) {
            int gid = tid + i * 256;
            int r = gid >> 4, gq = gid & 15;
            uint2 raw = *(const uint2*)(src + r * NPG + gq * 8);
            uint32_t p[4];
            p[0] = bf2pack((float)(raw.x & 255), (float)((raw.x >> 8) & 255));
            p[1] = bf2pack((float)((raw.x >> 16) & 255), (float)(raw.x >> 24));
            p[2] = bf2pack((float)(raw.y & 255), (float)((raw.y >> 8) & 255));
            p[3] = bf2pack((float)((raw.y >> 16) & 255), (float)(raw.y >> 24));
            uint32_t off = (uint32_t)(r * 256 + ((gq ^ (r & 7)) << 4));
            *(uint4*)(dst + off) = make_uint4(p[0], p[1], p[2], p[3]);
            int bsum = __dp4a(raw.x, 0x01010101u,
                              __dp4a(raw.y, 0x01010101u, 0u));
            atomicAdd(&rs[r], bsum);
        }
        __syncthreads();
        if (tid < NPG)
            (sel ? g_cout : g_cin)[g * NPG + tid] = rs[tid];
        __syncthreads();
    }
}

// ---------------------------------------------------------------------------
#define FUSED_SMEM (7 * BUFB)

__global__ void __launch_bounds__(512)
fused_kernel(const float* __restrict__ x,
             const float* __restrict__ bn_, const float* __restrict__ bo_,
             const float* __restrict__ lng_, const float* __restrict__ lnb_,
             const float* __restrict__ sIn,
             const float* __restrict__ flng, const float* __restrict__ flnb,
             const float* __restrict__ linw, const float* __restrict__ bias,
             float* __restrict__ dout) {
    extern __shared__ __align__(16) char dyn[];
    __shared__ float sbn[HD], sbo[HD], sgm[HD], sbt[HD];
    __shared__ float colsum[NC], xcs[NC];
    __shared__ __align__(8) unsigned long long mbars[3];

    int tid = threadIdx.x;
    int w = tid >> 5, lane = tid & 31;
    int m_blk = (w >> 2) * 32, n_blk = (w & 3) * 32;
    int grp = lane >> 2, tig = lane & 3;
    int g = blockIdx.x, row0 = g * 128;

    uint32_t base = smem_u32(dyn);
    uint32_t C0 = base, C1 = base + BUFB, Dd = base + 2 * BUFB;
    uint32_t A0 = base + 3 * BUFB, A1 = base + 4 * BUFB;
    uint32_t W0 = base + 5 * BUFB, W1 = base + 6 * BUFB;
    float* P  = (float*)(dyn + 3 * BUFB);
    float* PS = (float*)dyn;            // [128][4] LN partial sums (C0 region)
    float* PQ = (float*)(dyn + 2048);   // [128][4] LN partial sumsq

    uint32_t mbA = smem_u32(&mbars[0]);
    uint32_t mbB = smem_u32(&mbars[1]);
    uint32_t mbC = smem_u32(&mbars[2]);

    if (tid == 0) { mbar_init(mbA); mbar_init(mbB); mbar_init(mbC); }
    __syncthreads();

    int pa = 0, pb = 0, pc = 0;

    // issue layer-0 staging (adj + Wr) — overlaps the x-split below
    if (tid == 0) {
        mbar_expect(mbA, 4 * BUFB);
        bulk_g2s(C0, g_aimg[0][g], BUFB, mbA);
        bulk_g2s(C1, g_aimg[1][g], BUFB, mbA);
        bulk_g2s(W0, g_wimg[0][2][0], BUFB, mbA);
        bulk_g2s(W1, g_wimg[0][2][1], BUFB, mbA);
    }

    // --- layer-0 h: split x into A0/A1 ---
    #pragma unroll
    for (int i = 0; i < 4; i++) {
        int gid = tid + i * 512;
        int r = gid >> 4, gq = gid & 15;
        const float* src = x + (size_t)(row0 + r) * HD + gq * 8;
        float v[8];
        *(float4*)(v)     = *(const float4*)(src);
        *(float4*)(v + 4) = *(const float4*)(src + 4);
        uint32_t hi[4], lo[4];
        #pragma unroll
        for (int j = 0; j < 4; j++) {
            float a = v[2 * j], b = v[2 * j + 1];
            __nv_bfloat16 ha = __float2bfloat16(a), hb = __float2bfloat16(b);
            hi[j] = (uint32_t)__bfloat16_as_ushort(ha)
                  | ((uint32_t)__bfloat16_as_ushort(hb) << 16);
            lo[j] = bf2pack(a - __bfloat162float(ha), b - __bfloat162float(hb));
        }
        uint32_t off = (uint32_t)(r * 256 + ((gq ^ (r & 7)) << 4));
        *(uint4*)((char*)dyn + (A0 - base) + off) = make_uint4(hi[0], hi[1], hi[2], hi[3]);
        *(uint4*)((char*)dyn + (A1 - base) + off) = make_uint4(lo[0], lo[1], lo[2], lo[3]);
    }

    #pragma unroll 1
    for (int l = 0; l < NL; l++) {
        mbar_wait(mbA, (uint32_t)(pa & 1)); pa++;   // adj + Wr(l) ready
        if (tid < HD) {
            sbn[tid] = bn_[l * HD + tid];
            sbo[tid] = bo_[l * HD + tid];
            sgm[tid] = lng_[l * HD + tid];
            sbt[tid] = lnb_[l * HD + tid];
        }
        __syncthreads();   // x-split / LN writes visible; params loaded

        // root = h @ Wr^T (fused 3-term)
        float root[2][4][4];
        #pragma unroll
        for (int mt = 0; mt < 2; mt++)
            #pragma unroll
            for (int nt = 0; nt < 4; nt++)
                #pragma unroll
                for (int q = 0; q < 4; q++) root[mt][nt][q] = 0.f;
        pass3_nn(root, A0, A1, W0, W1, m_blk, n_blk, lane);
        __syncthreads();   // all warps done reading W0/W1
        if (tid == 0) {    // prefetch Wn -> W0/W1 (overlaps both adj passes)
            mbar_expect(mbB, 2 * BUFB);
            bulk_g2s(W0, g_wimg[l][0][0], BUFB, mbB);
            bulk_g2s(W1, g_wimg[l][0][1], BUFB, mbB);
        }

        // Hin = Ain @ (A0 + A1)
        float hacc[2][4][4];
        #pragma unroll
        for (int mt = 0; mt < 2; mt++)
            #pragma unroll
            for (int nt = 0; nt < 4; nt++)
                #pragma unroll
                for (int q = 0; q < 4; q++) hacc[mt][nt][q] = 0.f;
        pass2_nt(hacc, C0, A0, A1, m_blk, n_blk, lane);
        __syncthreads();   // all done reading C0 before overwrite
        #pragma unroll
        for (int mt = 0; mt < 2; mt++) {
            #pragma unroll
            for (int nt = 0; nt < 4; nt++) {
                int rg = m_blk + mt * 16 + grp;
                int cg = n_blk + nt * 8 + tig * 2;
                #pragma unroll
                for (int half = 0; half < 2; half++) {
                    int row = rg + half * 8;
                    float a = hacc[mt][nt][half * 2], b = hacc[mt][nt][half * 2 + 1];
                    __nv_bfloat16 ha = __float2bfloat16(a), hb = __float2bfloat16(b);
                    uint32_t off = swz(row, cg);
                    *(uint32_t*)((char*)dyn + (C0 - base) + off) =
                        (uint32_t)__bfloat16_as_ushort(ha)
                        | ((uint32_t)__bfloat16_as_ushort(hb) << 16);
                    *(uint32_t*)((char*)dyn + (Dd - base) + off) =
                        bf2pack(a - __bfloat162float(ha), b - __bfloat162float(hb));
                }
            }
        }

        // Hout = Aout @ (A0 + A1)
        #pragma unroll
        for (int mt = 0; mt < 2; mt++)
            #pragma unroll
            for (int nt = 0; nt < 4; nt++)
                #pragma unroll
                for (int q = 0; q < 4; q++) hacc[mt][nt][q] = 0.f;
        pass2_nt(hacc, C1, A0, A1, m_blk, n_blk, lane);
        __syncthreads();   // all done reading C1 + A0/A1 (h)
        if (tid == 0) {    // prefetch Wo-hi -> A0 (h-hi now dead)
            mbar_expect(mbC, BUFB);
            bulk_g2s(A0, g_wimg[l][1][0], BUFB, mbC);
        }
        #pragma unroll
        for (int mt = 0; mt < 2; mt++) {
            #pragma unroll
            for (int nt = 0; nt < 4; nt++) {
                int rg = m_blk + mt * 16 + grp;
                int cg = n_blk + nt * 8 + tig * 2;
                #pragma unroll
                for (int half = 0; half < 2; half++) {
                    int row = rg + half * 8;
                    float a = hacc[mt][nt][half * 2], b = hacc[mt][nt][half * 2 + 1];
                    __nv_bfloat16 ha = __float2bfloat16(a), hb = __float2bfloat16(b);
                    uint32_t off = swz(row, cg);
                    *(uint32_t*)((char*)dyn + (C1 - base) + off) =
                        (uint32_t)__bfloat16_as_ushort(ha)
                        | ((uint32_t)__bfloat16_as_ushort(hb) << 16);
                    *(uint32_t*)((char*)dyn + (A1 - base) + off) =
                        bf2pack(a - __bfloat162float(ha), b - __bfloat162float(hb));
                }
            }
        }
        __syncthreads();   // Hin/Hout stores visible
        mbar_wait(mbB, (uint32_t)(pb & 1)); pb++;   // Wn ready

        // agg = Hin @ Wn^T
        float agg[2][4][4];
        #pragma unroll
        for (int mt = 0; mt < 2; mt++)
            #pragma unroll
            for (int nt = 0; nt < 4; nt++)
                #pragma unroll
                for (int q = 0; q < 4; q++) agg[mt][nt][q] = 0.f;
        pass3_nn(agg, C0, Dd, W0, W1, m_blk, n_blk, lane);
        __syncthreads();   // done reading W1 (Wn-lo)
        if (tid == 0) {    // Wo-lo -> W1
            mbar_expect(mbA, BUFB);
            bulk_g2s(W1, g_wimg[l][1][1], BUFB, mbA);
        }
        mbar_wait(mbC, (uint32_t)(pc & 1)); pc++;   // Wo-hi in A0
        mbar_wait(mbA, (uint32_t)(pa & 1)); pa++;   // Wo-lo in W1

        // agg += Hout @ Wo^T  (Hhi=C1, Hlo=A1, Whi=A0, Wlo=W1)
        pass3_nn(agg, C1, A1, A0, W1, m_blk, n_blk, lane);
        __syncthreads();   // before partials overwrite C0 region

        // ---- epilogue + LN partials, direct from accumulators ----
        #pragma unroll
        for (int mt = 0; mt < 2; mt++) {
            #pragma unroll
            for (int half = 0; half < 2; half++) {
                int row = m_blk + mt * 16 + grp + half * 8;
                float ci = (float)g_cin[row0 + row];
                float co = (float)g_cout[row0 + row];
                float inv = 1.0f / fmaxf(ci + co, 1.0f);
                float ls = 0.f, lq = 0.f;
                #pragma unroll
                for (int nt = 0; nt < 4; nt++) {
                    int cg = n_blk + nt * 8 + tig * 2;
                    float v0 = (agg[mt][nt][half * 2]     + ci * sbn[cg]
                                + co * sbo[cg]) * inv + root[mt][nt][half * 2];
                    float v1 = (agg[mt][nt][half * 2 + 1] + ci * sbn[cg + 1]
                                + co * sbo[cg + 1]) * inv + root[mt][nt][half * 2 + 1];
                    agg[mt][nt][half * 2]     = v0;
                    agg[mt][nt][half * 2 + 1] = v1;
                    ls += v0 + v1;
                    lq += v0 * v0 + v1 * v1;
                }
                ls += __shfl_xor_sync(0xffffffffu, ls, 1);
                ls += __shfl_xor_sync(0xffffffffu, ls, 2);
                lq += __shfl_xor_sync(0xffffffffu, lq, 1);
                lq += __shfl_xor_sync(0xffffffffu, lq, 2);
                if (tig == 0) {
                    PS[row * 4 + (w & 3)] = ls;
                    PQ[row * 4 + (w & 3)] = lq;
                }
            }
        }
        __syncthreads();

        // ---- normalize + ReLU from registers; write next h or final P ----
        #pragma unroll
        for (int mt = 0; mt < 2; mt++) {
            #pragma unroll
            for (int half = 0; half < 2; half++) {
                int row = m_blk + mt * 16 + grp + half * 8;
                float sum = PS[row * 4 + 0] + PS[row * 4 + 1]
                          + PS[row * 4 + 2] + PS[row * 4 + 3];
                float sq  = PQ[row * 4 + 0] + PQ[row * 4 + 1]
                          + PQ[row * 4 + 2] + PQ[row * 4 + 3];
                float mu   = sum * (1.0f / 128.0f);
                float var  = sq * (1.0f / 128.0f) - mu * mu;
                float rstd = rsqrtf(var + 1e-5f);
                #pragma unroll
                for (int nt = 0; nt < 4; nt++) {
                    int cg = n_blk + nt * 8 + tig * 2;
                    float o0 = fmaxf((agg[mt][nt][half * 2]     - mu) * rstd
                                     * sgm[cg]     + sbt[cg],     0.f);
                    float o1 = fmaxf((agg[mt][nt][half * 2 + 1] - mu) * rstd
                                     * sgm[cg + 1] + sbt[cg + 1], 0.f);
                    if (l < NL - 1) {
                        uint32_t off = swz(row, cg);
                        __nv_bfloat16 h0 = __float2bfloat16(o0);
                        __nv_bfloat16 h1 = __float2bfloat16(o1);
                        *(uint32_t*)((char*)dyn + (A0 - base) + off) =
                            (uint32_t)__bfloat16_as_ushort(h0)
                            | ((uint32_t)__bfloat16_as_ushort(h1) << 16);
                        *(uint32_t*)((char*)dyn + (A1 - base) + off) =
                            bf2pack(o0 - __bfloat162float(h0),
                                    o1 - __bfloat162float(h1));
                    } else {
                        *(float2*)(P + row * 132 + cg) = make_float2(o0, o1);
                    }
                }
            }
        }

        if (l < NL - 1) {
            __syncthreads();   // partial reads done; C0/C1/W0/W1 free
            if (tid == 0) {    // next-layer adj + Wr
                mbar_expect(mbA, 4 * BUFB);
                bulk_g2s(C0, g_aimg[0][g], BUFB, mbA);
                bulk_g2s(C1, g_aimg[1][g], BUFB, mbA);
                bulk_g2s(W0, g_wimg[l + 1][2][0], BUFB, mbA);
                bulk_g2s(W1, g_wimg[l + 1][2][1], BUFB, mbA);
            }
        }
    }

    // =================== pooling head (in-CTA) ===================
    __syncthreads();
    float* sdP = (float*)dyn;
    float* plP = (float*)(dyn + 8192);

    *(float4*)(sdP + tid * 4) =
        *(const float4*)(sIn + (size_t)g * NPG * NC + tid * 4);
    __syncthreads();

    if (tid < NC) {
        float cs = 0.f;
        for (int n = 0; n < NPG; n++) cs += sdP[n * NC + tid];
        colsum[tid] = cs;
    }

    {
        int hcol = tid & 127, cgrp = tid >> 7;
        float pacc[4] = {0.f, 0.f, 0.f, 0.f};
        #pragma unroll 4
        for (int n = 0; n < NPG; n++) {
            float xv = P[n * 132 + hcol];
            #pragma unroll
            for (int c = 0; c < 4; c++)
                pacc[c] = fmaf(sdP[n * NC + cgrp * 4 + c], xv, pacc[c]);
        }
        #pragma unroll
        for (int c = 0; c < 4; c++)
            plP[(cgrp * 4 + c) * 128 + hcol] = pacc[c];
    }
    __syncthreads();

    {
        int rr = w;
        float4 v = *(float4*)(plP + rr * 128 + lane * 4);
        float sum = v.x + v.y + v.z + v.w;
        float sq  = v.x * v.x + v.y * v.y + v.z * v.z + v.w * v.w;
        #pragma unroll
        for (int o = 16; o; o >>= 1) {
            sum += __shfl_xor_sync(0xffffffffu, sum, o);
            sq  += __shfl_xor_sync(0xffffffffu, sq,  o);
        }
        float mu   = sum * (1.0f / 128.0f);
        float var  = sq * (1.0f / 128.0f) - mu * mu;
        float rstd = rsqrtf(var + 1e-5f);
        int f = lane * 4;
        float dot = ((v.x - mu) * rstd * flng[f + 0] + flnb[f + 0]) * linw[f + 0]
                  + ((v.y - mu) * rstd * flng[f + 1] + flnb[f + 1]) * linw[f + 1]
                  + ((v.z - mu) * rstd * flng[f + 2] + flnb[f + 2]) * linw[f + 2]
                  + ((v.w - mu) * rstd * flng[f + 3] + flnb[f + 3]) * linw[f + 3];
        #pragma unroll
        for (int o = 16; o; o >>= 1) dot += __shfl_xor_sync(0xffffffffu, dot, o);
        if (lane == 0) xcs[rr] = dot;
    }
    __syncthreads();

    if (tid == 0) {
        float ov = 0.f, l1 = 0.f, dn = 0.f;
        #pragma unroll
        for (int c = 0; c < NC; c++) {
            float mflag = (colsum[c] > 0.f) ? 1.f : 0.f;
            float v = xcs[c] * mflag;
            dout[257 + g * NC + c] = v;
            ov += v;
            l1 += fabsf(v);
            dn += mflag;
        }
        dout[g] = ov + bias[0];
        g_l1[g] = l1 / (dn + 1e-7f);
    }
}

// losses = 0.01*(sum|Wo|+sum|bo|) + 0.01*mean_g(l1[g])
__global__ void loss_kernel(const float* __restrict__ Wo,
                            const float* __restrict__ bo,
                            float* __restrict__ dout) {
    __shared__ float red[256];
    __shared__ float sreg;
    int tid = threadIdx.x;
    float rs = 0.f;
    for (int i = tid; i < NL * HD * HD; i += 256) rs += fabsf(Wo[i]);
    for (int i = tid; i < NL * HD; i += 256)      rs += fabsf(bo[i]);
    red[tid] = rs;
    __syncthreads();
    for (int o = 128; o; o >>= 1) {
        if (tid < o) red[tid] += red[tid + o];
        __syncthreads();
    }
    if (tid == 0) sreg = red[0];
    __syncthreads();
    float ls = (tid < NG) ? g_l1[tid] : 0.f;
    red[tid] = ls;
    __syncthreads();
    for (int o = 128; o; o >>= 1) {
        if (tid < o) red[tid] += red[tid + o];
        __syncthreads();
    }
    if (tid == 0)
        dout[256] = 0.01f * sreg + 0.01f * (red[0] / (float)NG);
}

// ---------------------------------------------------------------------------
extern "C" void kernel_launch(void* const* d_in, const int* in_sizes, int n_in,
                              void* d_out, int out_size) {
    const float* x    = (const float*)d_in[0];
    const void*  ei   = d_in[1];
    const void*  mk   = d_in[2];
    const float* s    = (const float*)d_in[3];
    const float* Wn   = (const float*)d_in[5];
    const float* bn   = (const float*)d_in[6];
    const float* Wo   = (const float*)d_in[7];
    const float* bo   = (const float*)d_in[8];
    const float* Wr   = (const float*)d_in[9];
    const float* lng  = (const float*)d_in[10];
    const float* lnb  = (const float*)d_in[11];
    const float* flng = (const float*)d_in[12];
    const float* flnb = (const float*)d_in[13];
    const float* linw = (const float*)d_in[14];
    const float* bias = (const float*)d_in[15];
    float* out = (float*)d_out;

    cudaFuncSetAttribute(fused_kernel,
                         cudaFuncAttributeMaxDynamicSharedMemorySize, FUSED_SMEM);

    prep_kernel<<<1034, 256>>>(Wn, Wo, Wr,
                               (const unsigned int*)ei,
                               (const unsigned int*)mk);
    adj_build_kernel<<<N_EDGES / 1024, 256>>>(ei, mk);
    aprep_kernel<<<NG, 256>>>();

    fused_kernel<<<NG, 512, FUSED_SMEM>>>(
        x, bn, bo, lng, lnb,
        s, flng, flnb, linw, bias, out);

    loss_kernel<<<1, 256>>>(Wo, bo, out);
}